// round 9
// baseline (speedup 1.0000x reference)
#include <cuda_runtime.h>
#include <cuda_bf16.h>
#include <cuda_fp16.h>
#include <cstdint>
#include <math.h>

#define BB 4
#define NN 512
#define DD 4
#define HH 256

// V staging layout: row stride 296 halfs (592B), second 128-half chunk at +136 halfs
#define VSTRIDE 296
#define VHALF2  136

// Dynamic smem layout (bytes)
#define OFF_W   0            // 2 x 16384 = 32768
#define OFF_A   32768        // 64 x 512  = 32768
#define OFF_V   65536        // 64*592+16 = 37904
#define OFF_U   103440       // 512
#define OFF_B2  103952       // 1024
#define OFF_ADJ 104976       // 2048
#define EDGE_SMEM 107024

// ---------------------------------------------------------------------------
// Device scratch (allocation-free rule)
// ---------------------------------------------------------------------------
__device__ __align__(16) __half g_u16[BB * NN * HH];  // x[b,j]@W_e1[0:4]        (fp16)
__device__ __align__(16) __half g_v16[BB * NN * HH];  // x[b,i]@W_e1[4:8]+b_e1   (fp16)
__device__ __align__(16) float  g_agg[BB * NN * HH];
__device__ __align__(16) float  g_adjT[BB * NN * NN]; // adjT[b][j][i]
// W_e2 fp16 mma B-fragments, two k-steps per uint4:
// [t(8)][g(32)][lane(32)] -> uint4{ b0(s=2t), b1(s=2t), b0(s=2t+1), b1(s=2t+1) }
__device__ __align__(16) uint4 g_Wh[8 * 32 * 32];

// ---------------------------------------------------------------------------
// PTX wrappers (baseline sm_80-class; compile clean for compute_103)
// ---------------------------------------------------------------------------
__device__ __forceinline__ uint32_t smem_to_u32(const void* p) {
    uint32_t a;
    asm("{ .reg .u64 t; cvta.to.shared.u64 t, %1; cvt.u32.u64 %0, t; }" : "=r"(a) : "l"(p));
    return a;
}

__device__ __forceinline__ void ldm4(uint32_t r[4], uint32_t addr) {
    asm volatile("ldmatrix.sync.aligned.m8n8.x4.shared.b16 {%0,%1,%2,%3}, [%4];"
                 : "=r"(r[0]), "=r"(r[1]), "=r"(r[2]), "=r"(r[3]) : "r"(addr));
}

__device__ __forceinline__ void mma_f16(float c[4], const uint32_t a[4],
                                        uint32_t b0, uint32_t b1) {
    asm volatile(
        "mma.sync.aligned.m16n8k16.row.col.f32.f16.f16.f32 "
        "{%0,%1,%2,%3}, {%4,%5,%6,%7}, {%8,%9}, {%0,%1,%2,%3};"
        : "+f"(c[0]), "+f"(c[1]), "+f"(c[2]), "+f"(c[3])
        : "r"(a[0]), "r"(a[1]), "r"(a[2]), "r"(a[3]), "r"(b0), "r"(b1));
}

__device__ __forceinline__ uint32_t pack_h2(float a, float b) {
    __half2 h = __floats2half2_rn(a, b);
    return *(uint32_t*)&h;
}

__device__ __forceinline__ uint32_t hrelu2(uint32_t va, uint32_t ua) {
    __half2 s = __hadd2(*(const __half2*)&va, *(const __half2*)&ua);
    __half2 z = __float2half2_rn(0.0f);
    __half2 r = __hmax2(s, z);
    return *(uint32_t*)&r;
}

__device__ __forceinline__ void cp_async16(uint32_t dst, const void* src) {
    asm volatile("cp.async.cg.shared.global [%0], [%1], 16;" :: "r"(dst), "l"(src));
}
#define CP_COMMIT() asm volatile("cp.async.commit_group;" ::: "memory")
#define CP_WAIT(N)  asm volatile("cp.async.wait_group %0;" :: "n"(N) : "memory")

// ---------------------------------------------------------------------------
// Kernel A: u, v in fp16
// ---------------------------------------------------------------------------
__global__ void prep_uv_kernel(const float* __restrict__ x,
                               const float* __restrict__ W_e1,
                               const float* __restrict__ b_e1) {
    int idx = blockIdx.x * blockDim.x + threadIdx.x;
    if (idx >= BB * NN * HH) return;
    int h  = idx & (HH - 1);
    int bn = idx >> 8;
    const float* xr = x + bn * DD;
    float su = 0.0f;
    float sv = b_e1[h];
    #pragma unroll
    for (int d = 0; d < DD; d++) {
        float xv = xr[d];
        su += xv * W_e1[d * HH + h];
        sv += xv * W_e1[(DD + d) * HH + h];
    }
    g_u16[idx] = __float2half_rn(su);
    g_v16[idx] = __float2half_rn(sv);
}

// ---------------------------------------------------------------------------
// Kernel W: pack W_e2 (fp16) into mma B-fragment layout, 2 k-steps per uint4
// ---------------------------------------------------------------------------
__global__ void wfrag_kernel(const float* __restrict__ W_e2) {
    int idx = blockIdx.x * blockDim.x + threadIdx.x;   // 8192
    if (idx >= 8 * 32 * 32) return;
    int lane = idx & 31;
    int g    = (idx >> 5) & 31;
    int t    = idx >> 10;
    int n  = g * 8 + (lane >> 2);
    int q  = lane & 3;
    int k0 = (2 * t) * 16 + q * 2;
    int k1 = (2 * t + 1) * 16 + q * 2;

    uint4 o;
    o.x = pack_h2(W_e2[(k0)     * HH + n], W_e2[(k0 + 1) * HH + n]);
    o.y = pack_h2(W_e2[(k0 + 8) * HH + n], W_e2[(k0 + 9) * HH + n]);
    o.z = pack_h2(W_e2[(k1)     * HH + n], W_e2[(k1 + 1) * HH + n]);
    o.w = pack_h2(W_e2[(k1 + 8) * HH + n], W_e2[(k1 + 9) * HH + n]);
    g_Wh[idx] = o;
}

// ---------------------------------------------------------------------------
// Kernel T: transpose adj -> adjT[b][j][i]
// ---------------------------------------------------------------------------
__global__ void adjT_kernel(const float* __restrict__ adj) {
    __shared__ float t[32][33];
    int b = blockIdx.z;
    int i0 = blockIdx.y * 32, j0 = blockIdx.x * 32;
    t[threadIdx.y][threadIdx.x] =
        adj[((size_t)b * NN + i0 + threadIdx.y) * NN + j0 + threadIdx.x];
    __syncthreads();
    g_adjT[((size_t)b * NN + j0 + threadIdx.y) * NN + i0 + threadIdx.x] =
        t[threadIdx.x][threadIdx.y];
}

// ---------------------------------------------------------------------------
// Kernel E: per (b,j) edge GEMM, fused bias+relu+adj-weighted i-reduction.
// 4 warps; warp tile 64(M) x 64(N). V staged per-iter, W staged per-t (2-deep
// smem ring via cp.async, distance-1, CP_WAIT(0) each step — one t-step
// (~970 cyc/SMSP) fully covers the cp.async L2 latency).
// The mma t-loop touches ONLY smem.
// ---------------------------------------------------------------------------
__global__ __launch_bounds__(128, 2)
void edge_mma_kernel(const float* __restrict__ b_e2) {
    extern __shared__ __align__(16) char smem[];
    __half* sW    = (__half*)(smem + OFF_W);     // [2][8192 halfs]
    __half* sA    = (__half*)(smem + OFF_A);
    __half* sV    = (__half*)(smem + OFF_V);
    __half* s_u16 = (__half*)(smem + OFF_U);
    float*  s_b2  = (float*)(smem + OFF_B2);
    float*  s_adj = (float*)(smem + OFF_ADJ);

    const int bid  = blockIdx.x;          // b*512 + j
    const int b    = bid >> 9;
    const int tid  = threadIdx.x;
    const int warp = tid >> 5;            // owns cols [warp*64, +64)
    const int lane = tid & 31;
    const int rg   = lane >> 2;
    const int q    = lane & 3;
    const int hi4  = lane >> 4;

    if (tid < 32)
        ((uint4*)s_u16)[tid] = ((const uint4*)(g_u16 + (size_t)bid * HH))[tid];
    s_b2[tid]       = b_e2[tid];
    s_b2[tid + 128] = b_e2[tid + 128];
    {
        const float* adjrow = g_adjT + ((size_t)b * NN + (bid & (NN - 1))) * NN;
        #pragma unroll
        for (int p = 0; p < 4; p++) s_adj[tid + p * 128] = adjrow[tid + p * 128];
    }

    const uint32_t swb   = (uint32_t)(lane & 7);
    const uint32_t svB   = smem_to_u32(sV);
    const uint32_t swB   = smem_to_u32(sW);
    const __half*  vbase = g_v16 + (size_t)b * NN * HH;

    // cp.async V constants: column chunk c = lane (fixed), rows warp+4p
    const uint32_t coff = (lane < 16) ? (uint32_t)(lane * 16)
                                      : (uint32_t)(272 + (lane - 16) * 16);
    const int csrc = lane * 8;            // halfs

    // build mapping: row ii = tid>>1, 128-half k-range kb
    const int ii = tid >> 1;
    const int kb = (tid & 1) * 128;
    const __half* vsrcS = sV + ii * VSTRIDE + ((tid & 1) ? VHALF2 : 0);
    const __half* usrc  = s_u16 + kb;
    char* adst = (char*)sA + ii * 512;
    const int sw = ii & 7;

    // ---- prologue: stage V(0) and W-slice 0, build A(0) ----
    {
        const __half* vg = vbase;
        #pragma unroll
        for (int p = 0; p < 16; p++) {
            int r = warp + p * 4;
            cp_async16(svB + (uint32_t)r * (VSTRIDE * 2) + coff, vg + (size_t)r * HH + csrc);
        }
        // W slice 0 -> buf 0
        const uint4* wsrc = g_Wh;         // slice 0
        #pragma unroll
        for (int p = 0; p < 8; p++)
            cp_async16(swB + (uint32_t)(tid * 8 + p) * 16, wsrc + tid * 8 + p);
        CP_COMMIT();
        CP_WAIT(0);
        __syncthreads();
        #pragma unroll
        for (int p = 0; p < 16; p++) {
            uint4 v = ((const uint4*)vsrcS)[p];
            uint4 u = ((const uint4*)usrc)[p];
            uint4 o;
            o.x = hrelu2(v.x, u.x);
            o.y = hrelu2(v.y, u.y);
            o.z = hrelu2(v.z, u.z);
            o.w = hrelu2(v.w, u.w);
            int c16 = (kb >> 3) + p;
            *(uint4*)(adst + ((c16 ^ sw) << 4)) = o;
        }
    }
    __syncthreads();

    float partial[16];
    #pragma unroll
    for (int c = 0; c < 16; c++) partial[c] = 0.0f;

    #pragma unroll 1
    for (int iter = 0; iter < 8; iter++) {
        const uint32_t rbase = smem_to_u32(sA) + (uint32_t)(lane & 15) * 512;
        float C[4][8][4];
        #pragma unroll
        for (int m = 0; m < 4; m++)
            #pragma unroll
            for (int j = 0; j < 8; j++)
                #pragma unroll
                for (int e = 0; e < 4; e++) C[m][j][e] = 0.0f;

        #pragma unroll 1
        for (int t = 0; t < 8; t++) {
            // (1) wait for the group committed last step: W(t) (+V when t==3).
            //     One t-step of mma issue (~970 cyc) covers the cp.async latency.
            CP_WAIT(0);
            // (2) all warps past last step's reads; W(t) data visible to all
            __syncthreads();
            // (3) prefetch W(t+1) into buf[(t+1)&1]; V(iter+1) joins the t==2 group
            {
                int nt = (t + 1) & 7;
                const uint4* wsrc = g_Wh + nt * 1024;
                uint32_t wdst = swB + (uint32_t)(((t + 1) & 1) * 16384);
                #pragma unroll
                for (int p = 0; p < 8; p++)
                    cp_async16(wdst + (uint32_t)(tid * 8 + p) * 16, wsrc + tid * 8 + p);
                if (t == 2 && iter < 7) {
                    const __half* vg = vbase + (size_t)((iter + 1) * 64) * HH;
                    #pragma unroll
                    for (int p = 0; p < 16; p++) {
                        int r = warp + p * 4;
                        cp_async16(svB + (uint32_t)r * (VSTRIDE * 2) + coff,
                                   vg + (size_t)r * HH + csrc);
                    }
                }
                CP_COMMIT();
            }
            // (4) mma: A frags via ldmatrix, W frags via LDS from sW[t&1]
            uint32_t a0[4][4], a1[4][4];
            uint32_t c0 = (uint32_t)(4 * t + hi4);
            #pragma unroll
            for (int m = 0; m < 4; m++) {
                uint32_t rb = rbase + (uint32_t)(m * 16) * 512;
                ldm4(a0[m], rb + (((c0)     ^ swb) << 4));
                ldm4(a1[m], rb + (((c0 + 2) ^ swb) << 4));
            }
            const uint4* wp = (const uint4*)(sW + (t & 1) * 8192) + (warp * 8) * 32 + lane;
            #pragma unroll
            for (int j = 0; j < 8; j++) {
                uint4 wf = wp[j * 32];
                #pragma unroll
                for (int m = 0; m < 4; m++) {
                    mma_f16(C[m][j], a0[m], wf.x, wf.y);
                    mma_f16(C[m][j], a1[m], wf.z, wf.w);
                }
            }
        }

        // ---- epilogue: bias + relu, adj-weight, accumulate over i ----
        #pragma unroll
        for (int m = 0; m < 4; m++) {
            float aw0 = s_adj[iter * 64 + m * 16 + rg];
            float aw1 = s_adj[iter * 64 + m * 16 + rg + 8];
            #pragma unroll
            for (int j = 0; j < 8; j++) {
                float bb0 = s_b2[warp * 64 + j * 8 + q * 2];
                float bb1 = s_b2[warp * 64 + j * 8 + q * 2 + 1];
                partial[j*2+0] += aw0 * fmaxf(C[m][j][0] + bb0, 0.0f)
                                + aw1 * fmaxf(C[m][j][2] + bb0, 0.0f);
                partial[j*2+1] += aw0 * fmaxf(C[m][j][1] + bb1, 0.0f)
                                + aw1 * fmaxf(C[m][j][3] + bb1, 0.0f);
            }
        }

        // ---- rebuild A in place from staged V(iter+1) ----
        // V group (t==2) was retired by CP_WAIT(0) at t==3; data visible after
        // the t==3 __syncthreads. This sync orders A reads before overwrite.
        __syncthreads();
        if (iter < 7) {
            #pragma unroll
            for (int p = 0; p < 16; p++) {
                uint4 v = ((const uint4*)vsrcS)[p];
                uint4 u = ((const uint4*)usrc)[p];
                uint4 o;
                o.x = hrelu2(v.x, u.x);
                o.y = hrelu2(v.y, u.y);
                o.z = hrelu2(v.z, u.z);
                o.w = hrelu2(v.w, u.w);
                int c16 = (kb >> 3) + p;
                *(uint4*)(adst + ((c16 ^ sw) << 4)) = o;
            }
            __syncthreads();   // A(iter+1) ready
        }
    }

    // ---- reduce over 8 row-groups (lanes stride 4); lanes 0-3 write ----
    #pragma unroll
    for (int c = 0; c < 16; c++) {
        float v = partial[c];
        v += __shfl_down_sync(0xffffffffu, v, 16);
        v += __shfl_down_sync(0xffffffffu, v, 8);
        v += __shfl_down_sync(0xffffffffu, v, 4);
        partial[c] = v;
    }
    if (lane < 4) {
        #pragma unroll
        for (int c = 0; c < 16; c++) {
            int col = warp * 64 + (c >> 1) * 8 + lane * 2 + (c & 1);
            g_agg[bid * HH + col] = partial[c];
        }
    }
}

// ---------------------------------------------------------------------------
// Kernel C: per-node MLP + log_softmax
// ---------------------------------------------------------------------------
__global__ __launch_bounds__(256, 4)
void tail_kernel(const float* __restrict__ x,
                 const float* __restrict__ W_n1, const float* __restrict__ b_n1,
                 const float* __restrict__ W_n2, const float* __restrict__ b_n2,
                 const float* __restrict__ W_o1, const float* __restrict__ b_o1,
                 const float* __restrict__ W_o,  const float* __restrict__ b_o,
                 float* __restrict__ out) {
    __shared__ float sA[8][256];
    __shared__ float sB[8][256];
    __shared__ float sx[8][4];

    const int row0 = blockIdx.x * 8;
    const int tid  = threadIdx.x;

    #pragma unroll
    for (int r = 0; r < 8; r++) sA[r][tid] = g_agg[(row0 + r) * HH + tid];
    if (tid < 32) sx[tid >> 2][tid & 3] = x[row0 * DD + tid];
    __syncthreads();

    {
        float acc[8];
        #pragma unroll
        for (int r = 0; r < 8; r++) acc[r] = b_n1[tid];
        #pragma unroll 4
        for (int k = 0; k < 256; k++) {
            float wv = W_n1[k * 256 + tid];
            #pragma unroll
            for (int r = 0; r < 8; r++) acc[r] += sA[r][k] * wv;
        }
        #pragma unroll
        for (int r = 0; r < 8; r++) sB[r][tid] = fmaxf(acc[r], 0.0f);
        __syncthreads();
    }
    {
        float acc[8];
        #pragma unroll
        for (int r = 0; r < 8; r++) acc[r] = b_n2[tid];
        #pragma unroll 4
        for (int k = 0; k < 256; k++) {
            float wv = W_n2[k * 256 + tid];
            #pragma unroll
            for (int r = 0; r < 8; r++) acc[r] += sB[r][k] * wv;
        }
        __syncthreads();
        #pragma unroll
        for (int r = 0; r < 8; r++) sA[r][tid] = fmaxf(acc[r], 0.0f);
        __syncthreads();
    }
    {
        float acc[8];
        #pragma unroll
        for (int r = 0; r < 8; r++) acc[r] = b_o1[tid];
        #pragma unroll
        for (int d = 0; d < 4; d++) {
            float wv = W_o1[d * 256 + tid];
            #pragma unroll
            for (int r = 0; r < 8; r++) acc[r] += sx[r][d] * wv;
        }
        #pragma unroll 4
        for (int k = 0; k < 256; k++) {
            float wv = W_o1[(4 + k) * 256 + tid];
            #pragma unroll
            for (int r = 0; r < 8; r++) acc[r] += sA[r][k] * wv;
        }
        __syncthreads();
        #pragma unroll
        for (int r = 0; r < 8; r++) sB[r][tid] = acc[r];
        __syncthreads();
    }
    if (tid < 32) {
        int r = tid >> 2, d = tid & 3;
        float acc = b_o[d];
        #pragma unroll 4
        for (int h = 0; h < 256; h++) acc += sB[r][h] * W_o[h * 4 + d];
        float m = acc;
        m = fmaxf(m, __shfl_xor_sync(0xffffffffu, m, 1));
        m = fmaxf(m, __shfl_xor_sync(0xffffffffu, m, 2));
        float e = expf(acc - m);
        float s = e;
        s += __shfl_xor_sync(0xffffffffu, s, 1);
        s += __shfl_xor_sync(0xffffffffu, s, 2);
        out[(row0 + r) * 4 + d] = acc - m - logf(s);
    }
}

// ---------------------------------------------------------------------------
// Launch
// ---------------------------------------------------------------------------
extern "C" void kernel_launch(void* const* d_in, const int* in_sizes, int n_in,
                              void* d_out, int out_size) {
    const float* x    = (const float*)d_in[0];
    const float* adj  = (const float*)d_in[1];
    const float* W_e1 = (const float*)d_in[2];
    const float* b_e1 = (const float*)d_in[3];
    const float* W_e2 = (const float*)d_in[4];
    const float* b_e2 = (const float*)d_in[5];
    const float* W_n1 = (const float*)d_in[6];
    const float* b_n1 = (const float*)d_in[7];
    const float* W_n2 = (const float*)d_in[8];
    const float* b_n2 = (const float*)d_in[9];
    const float* W_o1 = (const float*)d_in[10];
    const float* b_o1 = (const float*)d_in[11];
    const float* W_o  = (const float*)d_in[12];
    const float* b_o  = (const float*)d_in[13];
    float* out = (float*)d_out;

    static bool attr_set = false;
    if (!attr_set) {
        cudaFuncSetAttribute(edge_mma_kernel,
                             cudaFuncAttributeMaxDynamicSharedMemorySize, EDGE_SMEM);
        attr_set = true;
    }

    prep_uv_kernel<<<(BB * NN * HH) / 256, 256>>>(x, W_e1, b_e1);
    wfrag_kernel<<<32, 256>>>(W_e2);
    adjT_kernel<<<dim3(16, 16, 4), dim3(32, 32)>>>(adj);
    edge_mma_kernel<<<BB * NN, 128, EDGE_SMEM>>>(b_e2);
    tail_kernel<<<(BB * NN) / 8, 256>>>(x, W_n1, b_n1, W_n2, b_n2,
                                        W_o1, b_o1, W_o, b_o, out);
}

// round 10
// speedup vs baseline: 1.1340x; 1.1340x over previous
#include <cuda_runtime.h>
#include <cuda_bf16.h>
#include <cuda_fp16.h>
#include <cstdint>
#include <math.h>

#define BB 4
#define NN 512
#define DD 4
#define HH 256

// V staging: row stride 296 halfs (592B); halfs [0,128) at byte 0, [128,256) at byte 272
#define VSTRIDE 296

// Dynamic smem layout (bytes)
#define OFF_A   0            // 64 x 512          = 32768
#define OFF_V   32768        // 64*592 + 16       = 37904
#define OFF_U   70672        // 512
#define OFF_B2  71184        // 1024
#define OFF_ADJ 72208        // 2048
#define OFF_RED 74256        // 4*4*16 floats     = 1024
#define EDGE_SMEM 75280

// ---------------------------------------------------------------------------
// Device scratch (allocation-free rule)
// ---------------------------------------------------------------------------
__device__ __align__(16) __half g_u16[BB * NN * HH];  // x[b,j]@W_e1[0:4]        (fp16)
__device__ __align__(16) __half g_v16[BB * NN * HH];  // x[b,i]@W_e1[4:8]+b_e1   (fp16)
__device__ __align__(16) float  g_agg[BB * NN * HH];
__device__ __align__(16) float  g_adjT[BB * NN * NN]; // adjT[b][j][i]
// W_e2 fp16 mma B-fragments, two k-steps per uint4:
// [t(8)][g(32)][lane(32)] -> uint4{ b0(s=2t), b1(s=2t), b0(s=2t+1), b1(s=2t+1) }
__device__ __align__(16) uint4 g_Wh[8 * 32 * 32];

// ---------------------------------------------------------------------------
// PTX wrappers (baseline sm_80-class; compile clean for compute_103)
// ---------------------------------------------------------------------------
__device__ __forceinline__ uint32_t smem_to_u32(const void* p) {
    uint32_t a;
    asm("{ .reg .u64 t; cvta.to.shared.u64 t, %1; cvt.u32.u64 %0, t; }" : "=r"(a) : "l"(p));
    return a;
}

__device__ __forceinline__ void ldm4(uint32_t r[4], uint32_t addr) {
    asm volatile("ldmatrix.sync.aligned.m8n8.x4.shared.b16 {%0,%1,%2,%3}, [%4];"
                 : "=r"(r[0]), "=r"(r[1]), "=r"(r[2]), "=r"(r[3]) : "r"(addr));
}

__device__ __forceinline__ void mma_f16(float c[4], const uint32_t a[4],
                                        uint32_t b0, uint32_t b1) {
    asm volatile(
        "mma.sync.aligned.m16n8k16.row.col.f32.f16.f16.f32 "
        "{%0,%1,%2,%3}, {%4,%5,%6,%7}, {%8,%9}, {%0,%1,%2,%3};"
        : "+f"(c[0]), "+f"(c[1]), "+f"(c[2]), "+f"(c[3])
        : "r"(a[0]), "r"(a[1]), "r"(a[2]), "r"(a[3]), "r"(b0), "r"(b1));
}

__device__ __forceinline__ uint32_t pack_h2(float a, float b) {
    __half2 h = __floats2half2_rn(a, b);
    return *(uint32_t*)&h;
}

__device__ __forceinline__ uint32_t hrelu2(uint32_t va, uint32_t ua) {
    __half2 s = __hadd2(*(const __half2*)&va, *(const __half2*)&ua);
    __half2 z = __float2half2_rn(0.0f);
    __half2 r = __hmax2(s, z);
    return *(uint32_t*)&r;
}

__device__ __forceinline__ void cp_async16(uint32_t dst, const void* src) {
    asm volatile("cp.async.cg.shared.global [%0], [%1], 16;" :: "r"(dst), "l"(src));
}
#define CP_COMMIT() asm volatile("cp.async.commit_group;" ::: "memory")
#define CP_WAIT(N)  asm volatile("cp.async.wait_group %0;" :: "n"(N) : "memory")

// ---------------------------------------------------------------------------
// Kernel A: u, v in fp16
// ---------------------------------------------------------------------------
__global__ void prep_uv_kernel(const float* __restrict__ x,
                               const float* __restrict__ W_e1,
                               const float* __restrict__ b_e1) {
    int idx = blockIdx.x * blockDim.x + threadIdx.x;
    if (idx >= BB * NN * HH) return;
    int h  = idx & (HH - 1);
    int bn = idx >> 8;
    const float* xr = x + bn * DD;
    float su = 0.0f;
    float sv = b_e1[h];
    #pragma unroll
    for (int d = 0; d < DD; d++) {
        float xv = xr[d];
        su += xv * W_e1[d * HH + h];
        sv += xv * W_e1[(DD + d) * HH + h];
    }
    g_u16[idx] = __float2half_rn(su);
    g_v16[idx] = __float2half_rn(sv);
}

// ---------------------------------------------------------------------------
// Kernel W: pack W_e2 (fp16) into mma B-fragment layout, 2 k-steps per uint4
// ---------------------------------------------------------------------------
__global__ void wfrag_kernel(const float* __restrict__ W_e2) {
    int idx = blockIdx.x * blockDim.x + threadIdx.x;   // 8192
    if (idx >= 8 * 32 * 32) return;
    int lane = idx & 31;
    int g    = (idx >> 5) & 31;
    int t    = idx >> 10;
    int n  = g * 8 + (lane >> 2);
    int q  = lane & 3;
    int k0 = (2 * t) * 16 + q * 2;
    int k1 = (2 * t + 1) * 16 + q * 2;

    uint4 o;
    o.x = pack_h2(W_e2[(k0)     * HH + n], W_e2[(k0 + 1) * HH + n]);
    o.y = pack_h2(W_e2[(k0 + 8) * HH + n], W_e2[(k0 + 9) * HH + n]);
    o.z = pack_h2(W_e2[(k1)     * HH + n], W_e2[(k1 + 1) * HH + n]);
    o.w = pack_h2(W_e2[(k1 + 8) * HH + n], W_e2[(k1 + 9) * HH + n]);
    g_Wh[idx] = o;
}

// ---------------------------------------------------------------------------
// Kernel T: transpose adj -> adjT[b][j][i]
// ---------------------------------------------------------------------------
__global__ void adjT_kernel(const float* __restrict__ adj) {
    __shared__ float t[32][33];
    int b = blockIdx.z;
    int i0 = blockIdx.y * 32, j0 = blockIdx.x * 32;
    t[threadIdx.y][threadIdx.x] =
        adj[((size_t)b * NN + i0 + threadIdx.y) * NN + j0 + threadIdx.x];
    __syncthreads();
    g_adjT[((size_t)b * NN + j0 + threadIdx.y) * NN + i0 + threadIdx.x] =
        t[threadIdx.x][threadIdx.y];
}

// ---------------------------------------------------------------------------
// Kernel E: per (b,j) edge GEMM, fused bias+relu+adj-weighted i-reduction.
// 8 warps = 2(M halves of 64-row i-tile) x 4(N groups of 64 cols).
// V staged per-iter via cp.async (L1-bypassing stream, reuse-free) — R7 pipeline.
// W read via LDG (L1-resident across iters). mma t-loop: smem + L1 only.
// ---------------------------------------------------------------------------
__global__ __launch_bounds__(256, 2)
void edge_mma_kernel(const float* __restrict__ b_e2) {
    extern __shared__ __align__(16) char smem[];
    __half* sA    = (__half*)(smem + OFF_A);
    __half* sV    = (__half*)(smem + OFF_V);
    __half* s_u16 = (__half*)(smem + OFF_U);
    float*  s_b2  = (float*)(smem + OFF_B2);
    float*  s_adj = (float*)(smem + OFF_ADJ);
    float*  sred  = (float*)(smem + OFF_RED);   // [4][4][16]

    const int bid  = blockIdx.x;          // b*512 + j
    const int b    = bid >> 9;
    const int tid  = threadIdx.x;
    const int warp = tid >> 5;
    const int lane = tid & 31;
    const int warp_m = warp & 1;          // 32-row half
    const int warp_n = warp >> 1;         // 64-col group
    const int rg   = lane >> 2;
    const int q    = lane & 3;
    const int hi4  = lane >> 4;

    if (tid < 32)
        ((uint4*)s_u16)[tid] = ((const uint4*)(g_u16 + (size_t)bid * HH))[tid];
    s_b2[tid] = b_e2[tid];
    {
        const float* adjrow = g_adjT + ((size_t)b * NN + (bid & (NN - 1))) * NN;
        s_adj[tid]       = adjrow[tid];
        s_adj[tid + 256] = adjrow[tid + 256];
    }

    const uint32_t svB   = smem_to_u32(sV);
    const __half*  vbase = g_v16 + (size_t)b * NN * HH;

    // cp.async V constants: column chunk = lane, rows warp + p*8 (8 rows/thread)
    const uint32_t coff = (lane < 16) ? (uint32_t)(lane * 16)
                                      : (uint32_t)(272 + (lane - 16) * 16);
    const int csrc = lane * 8;            // halfs

    // builder mapping: row ii = tid>>2, quarter kq = (tid&3)*64 halfs
    const int ii = tid >> 2;
    const int kq = (tid & 3) * 64;
    const int voff = ((tid & 2) ? 136 : 0) + ((tid & 1) ? 64 : 0);   // halfs
    const __half* vsrcS = sV + ii * VSTRIDE + voff;
    const __half* usrc  = s_u16 + kq;
    char* adst = (char*)sA + ii * 512;
    const int sw = ii & 7;

    // mma A-read constants
    const int rowA = warp_m * 32 + (lane & 15);
    const uint32_t swb   = (uint32_t)(rowA & 7);
    const uint32_t base0 = smem_to_u32(sA) + (uint32_t)rowA * 512;
    const uint32_t base1 = base0 + 16 * 512;

    // ---- prologue: stage V(0), build A(0) ----
    {
        const __half* vg = vbase;
        #pragma unroll
        for (int p = 0; p < 8; p++) {
            int r = warp + p * 8;
            cp_async16(svB + (uint32_t)r * (VSTRIDE * 2) + coff, vg + (size_t)r * HH + csrc);
        }
        CP_COMMIT();
        CP_WAIT(0);
        __syncthreads();
        #pragma unroll
        for (int p = 0; p < 8; p++) {
            uint4 v = ((const uint4*)vsrcS)[p];
            uint4 u = ((const uint4*)usrc)[p];
            uint4 o;
            o.x = hrelu2(v.x, u.x);
            o.y = hrelu2(v.y, u.y);
            o.z = hrelu2(v.z, u.z);
            o.w = hrelu2(v.w, u.w);
            int c16 = (kq >> 3) + p;
            *(uint4*)(adst + ((c16 ^ sw) << 4)) = o;
        }
    }
    __syncthreads();

    float partial[16];
    #pragma unroll
    for (int c = 0; c < 16; c++) partial[c] = 0.0f;

    #pragma unroll 1
    for (int iter = 0; iter < 8; iter++) {
        // ---- stage V(iter+1) (fire and forget; .cg bypasses L1 so W stays hot) ----
        if (iter < 7) {
            const __half* vg = vbase + (size_t)((iter + 1) * 64) * HH;
            #pragma unroll
            for (int p = 0; p < 8; p++) {
                int r = warp + p * 8;
                cp_async16(svB + (uint32_t)r * (VSTRIDE * 2) + coff, vg + (size_t)r * HH + csrc);
            }
            CP_COMMIT();
        }

        // ---- mma t-loop: warp computes rows [warp_m*32,+32) x cols [warp_n*64,+64) ----
        float C[2][8][4];
        #pragma unroll
        for (int m = 0; m < 2; m++)
            #pragma unroll
            for (int j = 0; j < 8; j++)
                #pragma unroll
                for (int e = 0; e < 4; e++) C[m][j][e] = 0.0f;

        #pragma unroll 1
        for (int t = 0; t < 8; t++) {
            uint32_t a0[2][4], a1[2][4];
            uint32_t c0 = (uint32_t)(4 * t + hi4);
            ldm4(a0[0], base0 + (((c0)     ^ swb) << 4));
            ldm4(a1[0], base0 + (((c0 + 2) ^ swb) << 4));
            ldm4(a0[1], base1 + (((c0)     ^ swb) << 4));
            ldm4(a1[1], base1 + (((c0 + 2) ^ swb) << 4));
            const uint4* wp = g_Wh + ((t * 32) + warp_n * 8) * 32 + lane;
            #pragma unroll
            for (int j = 0; j < 8; j++) {
                uint4 wf = wp[j * 32];
                mma_f16(C[0][j], a0[0], wf.x, wf.y);
                mma_f16(C[1][j], a0[1], wf.x, wf.y);
                mma_f16(C[0][j], a1[0], wf.z, wf.w);
                mma_f16(C[1][j], a1[1], wf.z, wf.w);
            }
        }

        // ---- epilogue: bias + relu, adj-weight, accumulate over i ----
        const int ir = iter * 64 + warp_m * 32;
        #pragma unroll
        for (int m = 0; m < 2; m++) {
            float aw0 = s_adj[ir + m * 16 + rg];
            float aw1 = s_adj[ir + m * 16 + rg + 8];
            #pragma unroll
            for (int j = 0; j < 8; j++) {
                float bb0 = s_b2[warp_n * 64 + j * 8 + q * 2];
                float bb1 = s_b2[warp_n * 64 + j * 8 + q * 2 + 1];
                partial[j*2+0] += aw0 * fmaxf(C[m][j][0] + bb0, 0.0f)
                                + aw1 * fmaxf(C[m][j][2] + bb0, 0.0f);
                partial[j*2+1] += aw0 * fmaxf(C[m][j][1] + bb1, 0.0f)
                                + aw1 * fmaxf(C[m][j][3] + bb1, 0.0f);
            }
        }

        // ---- wait V(iter+1), rebuild A in place ----
        if (iter < 7) { CP_WAIT(0); }
        __syncthreads();   // A fully consumed by all warps; V arrival visible
        if (iter < 7) {
            #pragma unroll
            for (int p = 0; p < 8; p++) {
                uint4 v = ((const uint4*)vsrcS)[p];
                uint4 u = ((const uint4*)usrc)[p];
                uint4 o;
                o.x = hrelu2(v.x, u.x);
                o.y = hrelu2(v.y, u.y);
                o.z = hrelu2(v.z, u.z);
                o.w = hrelu2(v.w, u.w);
                int c16 = (kq >> 3) + p;
                *(uint4*)(adst + ((c16 ^ sw) << 4)) = o;
            }
            __syncthreads();   // A(iter+1) ready
        }
    }

    // ---- reduce over 8 row-groups within each warp (lanes stride 4) ----
    #pragma unroll
    for (int c = 0; c < 16; c++) {
        float v = partial[c];
        v += __shfl_down_sync(0xffffffffu, v, 16);
        v += __shfl_down_sync(0xffffffffu, v, 8);
        v += __shfl_down_sync(0xffffffffu, v, 4);
        partial[c] = v;
    }
    // ---- combine warp_m pair via smem, write agg ----
    if (warp_m == 1 && lane < 4) {
        #pragma unroll
        for (int c = 0; c < 16; c++) sred[(warp_n * 4 + lane) * 16 + c] = partial[c];
    }
    __syncthreads();
    if (warp_m == 0 && lane < 4) {
        #pragma unroll
        for (int c = 0; c < 16; c++) {
            float v = partial[c] + sred[(warp_n * 4 + lane) * 16 + c];
            int col = warp_n * 64 + (c >> 1) * 8 + lane * 2 + (c & 1);
            g_agg[bid * HH + col] = v;
        }
    }
}

// ---------------------------------------------------------------------------
// Kernel C: per-node MLP + log_softmax
// ---------------------------------------------------------------------------
__global__ __launch_bounds__(256, 4)
void tail_kernel(const float* __restrict__ x,
                 const float* __restrict__ W_n1, const float* __restrict__ b_n1,
                 const float* __restrict__ W_n2, const float* __restrict__ b_n2,
                 const float* __restrict__ W_o1, const float* __restrict__ b_o1,
                 const float* __restrict__ W_o,  const float* __restrict__ b_o,
                 float* __restrict__ out) {
    __shared__ float sA[8][256];
    __shared__ float sB[8][256];
    __shared__ float sx[8][4];

    const int row0 = blockIdx.x * 8;
    const int tid  = threadIdx.x;

    #pragma unroll
    for (int r = 0; r < 8; r++) sA[r][tid] = g_agg[(row0 + r) * HH + tid];
    if (tid < 32) sx[tid >> 2][tid & 3] = x[row0 * DD + tid];
    __syncthreads();

    {
        float acc[8];
        #pragma unroll
        for (int r = 0; r < 8; r++) acc[r] = b_n1[tid];
        #pragma unroll 4
        for (int k = 0; k < 256; k++) {
            float wv = W_n1[k * 256 + tid];
            #pragma unroll
            for (int r = 0; r < 8; r++) acc[r] += sA[r][k] * wv;
        }
        #pragma unroll
        for (int r = 0; r < 8; r++) sB[r][tid] = fmaxf(acc[r], 0.0f);
        __syncthreads();
    }
    {
        float acc[8];
        #pragma unroll
        for (int r = 0; r < 8; r++) acc[r] = b_n2[tid];
        #pragma unroll 4
        for (int k = 0; k < 256; k++) {
            float wv = W_n2[k * 256 + tid];
            #pragma unroll
            for (int r = 0; r < 8; r++) acc[r] += sB[r][k] * wv;
        }
        __syncthreads();
        #pragma unroll
        for (int r = 0; r < 8; r++) sA[r][tid] = fmaxf(acc[r], 0.0f);
        __syncthreads();
    }
    {
        float acc[8];
        #pragma unroll
        for (int r = 0; r < 8; r++) acc[r] = b_o1[tid];
        #pragma unroll
        for (int d = 0; d < 4; d++) {
            float wv = W_o1[d * 256 + tid];
            #pragma unroll
            for (int r = 0; r < 8; r++) acc[r] += sx[r][d] * wv;
        }
        #pragma unroll 4
        for (int k = 0; k < 256; k++) {
            float wv = W_o1[(4 + k) * 256 + tid];
            #pragma unroll
            for (int r = 0; r < 8; r++) acc[r] += sA[r][k] * wv;
        }
        __syncthreads();
        #pragma unroll
        for (int r = 0; r < 8; r++) sB[r][tid] = acc[r];
        __syncthreads();
    }
    if (tid < 32) {
        int r = tid >> 2, d = tid & 3;
        float acc = b_o[d];
        #pragma unroll 4
        for (int h = 0; h < 256; h++) acc += sB[r][h] * W_o[h * 4 + d];
        float m = acc;
        m = fmaxf(m, __shfl_xor_sync(0xffffffffu, m, 1));
        m = fmaxf(m, __shfl_xor_sync(0xffffffffu, m, 2));
        float e = expf(acc - m);
        float s = e;
        s += __shfl_xor_sync(0xffffffffu, s, 1);
        s += __shfl_xor_sync(0xffffffffu, s, 2);
        out[(row0 + r) * 4 + d] = acc - m - logf(s);
    }
}

// ---------------------------------------------------------------------------
// Launch
// ---------------------------------------------------------------------------
extern "C" void kernel_launch(void* const* d_in, const int* in_sizes, int n_in,
                              void* d_out, int out_size) {
    const float* x    = (const float*)d_in[0];
    const float* adj  = (const float*)d_in[1];
    const float* W_e1 = (const float*)d_in[2];
    const float* b_e1 = (const float*)d_in[3];
    const float* W_e2 = (const float*)d_in[4];
    const float* b_e2 = (const float*)d_in[5];
    const float* W_n1 = (const float*)d_in[6];
    const float* b_n1 = (const float*)d_in[7];
    const float* W_n2 = (const float*)d_in[8];
    const float* b_n2 = (const float*)d_in[9];
    const float* W_o1 = (const float*)d_in[10];
    const float* b_o1 = (const float*)d_in[11];
    const float* W_o  = (const float*)d_in[12];
    const float* b_o  = (const float*)d_in[13];
    float* out = (float*)d_out;

    static bool attr_set = false;
    if (!attr_set) {
        cudaFuncSetAttribute(edge_mma_kernel,
                             cudaFuncAttributeMaxDynamicSharedMemorySize, EDGE_SMEM);
        attr_set = true;
    }

    prep_uv_kernel<<<(BB * NN * HH) / 256, 256>>>(x, W_e1, b_e1);
    wfrag_kernel<<<32, 256>>>(W_e2);
    adjT_kernel<<<dim3(16, 16, 4), dim3(32, 32)>>>(adj);
    edge_mma_kernel<<<BB * NN, 256, EDGE_SMEM>>>(b_e2);
    tail_kernel<<<(BB * NN) / 8, 256>>>(x, W_n1, b_n1, W_n2, b_n2,
                                        W_o1, b_o1, W_o, b_o, out);
}

// round 11
// speedup vs baseline: 2.1805x; 1.9228x over previous
#include <cuda_runtime.h>
#include <cuda_bf16.h>
#include <cuda_fp16.h>
#include <cstdint>
#include <math.h>

#define BB 4
#define NN 512
#define DD 4
#define HH 256

// V staging layout: row stride 296 halfs (592B), second 128-half chunk at +136 halfs
#define VSTRIDE 296
#define VHALF2  136

// ---------------------------------------------------------------------------
// Device scratch (allocation-free rule)
// ---------------------------------------------------------------------------
__device__ __align__(16) __half g_u16[BB * NN * HH];  // x[b,j]@W_e1[0:4]        (fp16)
__device__ __align__(16) __half g_v16[BB * NN * HH];  // x[b,i]@W_e1[4:8]+b_e1   (fp16)
__device__ __align__(16) float  g_agg[BB * NN * HH];
__device__ __align__(16) float  g_adjT[BB * NN * NN]; // adjT[b][j][i]
// W_e2 fp16 mma B-fragments, two k-steps per uint4:
// [t(8)][g(32)][lane(32)] -> uint4{ b0(s=2t), b1(s=2t), b0(s=2t+1), b1(s=2t+1) }
__device__ __align__(16) uint4 g_Wh[8 * 32 * 32];

// ---------------------------------------------------------------------------
// PTX wrappers (baseline sm_80-class; compile clean for compute_103)
// ---------------------------------------------------------------------------
__device__ __forceinline__ uint32_t smem_to_u32(const void* p) {
    uint32_t a;
    asm("{ .reg .u64 t; cvta.to.shared.u64 t, %1; cvt.u32.u64 %0, t; }" : "=r"(a) : "l"(p));
    return a;
}

__device__ __forceinline__ void ldm4(uint32_t r[4], uint32_t addr) {
    asm volatile("ldmatrix.sync.aligned.m8n8.x4.shared.b16 {%0,%1,%2,%3}, [%4];"
                 : "=r"(r[0]), "=r"(r[1]), "=r"(r[2]), "=r"(r[3]) : "r"(addr));
}

__device__ __forceinline__ void mma_f16(float c[4], const uint32_t a[4],
                                        uint32_t b0, uint32_t b1) {
    asm volatile(
        "mma.sync.aligned.m16n8k16.row.col.f32.f16.f16.f32 "
        "{%0,%1,%2,%3}, {%4,%5,%6,%7}, {%8,%9}, {%0,%1,%2,%3};"
        : "+f"(c[0]), "+f"(c[1]), "+f"(c[2]), "+f"(c[3])
        : "r"(a[0]), "r"(a[1]), "r"(a[2]), "r"(a[3]), "r"(b0), "r"(b1));
}

__device__ __forceinline__ uint32_t pack_h2(float a, float b) {
    __half2 h = __floats2half2_rn(a, b);
    return *(uint32_t*)&h;
}

__device__ __forceinline__ uint32_t hrelu2(uint32_t va, uint32_t ua) {
    __half2 s = __hadd2(*(const __half2*)&va, *(const __half2*)&ua);
    __half2 z = __float2half2_rn(0.0f);
    __half2 r = __hmax2(s, z);
    return *(uint32_t*)&r;
}

__device__ __forceinline__ void cp_async16(uint32_t dst, const void* src) {
    asm volatile("cp.async.cg.shared.global [%0], [%1], 16;" :: "r"(dst), "l"(src));
}
#define CP_COMMIT() asm volatile("cp.async.commit_group;" ::: "memory")
#define CP_WAIT(N)  asm volatile("cp.async.wait_group %0;" :: "n"(N) : "memory")

// ---------------------------------------------------------------------------
// Kernel A: u, v in fp16
// ---------------------------------------------------------------------------
__global__ void prep_uv_kernel(const float* __restrict__ x,
                               const float* __restrict__ W_e1,
                               const float* __restrict__ b_e1) {
    int idx = blockIdx.x * blockDim.x + threadIdx.x;
    if (idx >= BB * NN * HH) return;
    int h  = idx & (HH - 1);
    int bn = idx >> 8;
    const float* xr = x + bn * DD;
    float su = 0.0f;
    float sv = b_e1[h];
    #pragma unroll
    for (int d = 0; d < DD; d++) {
        float xv = xr[d];
        su += xv * W_e1[d * HH + h];
        sv += xv * W_e1[(DD + d) * HH + h];
    }
    g_u16[idx] = __float2half_rn(su);
    g_v16[idx] = __float2half_rn(sv);
}

// ---------------------------------------------------------------------------
// Kernel W: pack W_e2 (fp16) into mma B-fragment layout, 2 k-steps per uint4
// ---------------------------------------------------------------------------
__global__ void wfrag_kernel(const float* __restrict__ W_e2) {
    int idx = blockIdx.x * blockDim.x + threadIdx.x;   // 8192
    if (idx >= 8 * 32 * 32) return;
    int lane = idx & 31;
    int g    = (idx >> 5) & 31;
    int t    = idx >> 10;
    int n  = g * 8 + (lane >> 2);
    int q  = lane & 3;
    int k0 = (2 * t) * 16 + q * 2;
    int k1 = (2 * t + 1) * 16 + q * 2;

    uint4 o;
    o.x = pack_h2(W_e2[(k0)     * HH + n], W_e2[(k0 + 1) * HH + n]);
    o.y = pack_h2(W_e2[(k0 + 8) * HH + n], W_e2[(k0 + 9) * HH + n]);
    o.z = pack_h2(W_e2[(k1)     * HH + n], W_e2[(k1 + 1) * HH + n]);
    o.w = pack_h2(W_e2[(k1 + 8) * HH + n], W_e2[(k1 + 9) * HH + n]);
    g_Wh[idx] = o;
}

// ---------------------------------------------------------------------------
// Kernel T: transpose adj -> adjT[b][j][i]
// ---------------------------------------------------------------------------
__global__ void adjT_kernel(const float* __restrict__ adj) {
    __shared__ float t[32][33];
    int b = blockIdx.z;
    int i0 = blockIdx.y * 32, j0 = blockIdx.x * 32;
    t[threadIdx.y][threadIdx.x] =
        adj[((size_t)b * NN + i0 + threadIdx.y) * NN + j0 + threadIdx.x];
    __syncthreads();
    g_adjT[((size_t)b * NN + j0 + threadIdx.y) * NN + i0 + threadIdx.x] =
        t[threadIdx.x][threadIdx.y];
}

// ---------------------------------------------------------------------------
// Kernel E: per (b,j) edge GEMM, fused bias+relu+adj-weighted i-reduction.
// 4 warps; warp tile 64(M) x 64(N). A single-buffered; next v tile staged in
// smem via cp.async. mma t-loop: smem + L1 W-frags, with W fragments
// software-pipelined 2-deep through registers (load wf[j+2] before mma wf[j]).
// ---------------------------------------------------------------------------
__global__ __launch_bounds__(128, 2)
void edge_mma_kernel(const float* __restrict__ b_e2) {
    __shared__ __align__(16) __half s_u16[HH];
    __shared__ float s_b2[HH];
    __shared__ float s_adj[NN];
    __shared__ __align__(16) __half sA[64 * 256];
    __shared__ __align__(16) __half sV[64 * VSTRIDE + 8];

    const int bid  = blockIdx.x;          // b*512 + j
    const int b    = bid >> 9;
    const int tid  = threadIdx.x;
    const int warp = tid >> 5;            // owns cols [warp*64, +64)
    const int lane = tid & 31;
    const int rg   = lane >> 2;
    const int q    = lane & 3;
    const int hi4  = lane >> 4;

    if (tid < 32)
        ((uint4*)s_u16)[tid] = ((const uint4*)(g_u16 + (size_t)bid * HH))[tid];
    s_b2[tid]       = b_e2[tid];
    s_b2[tid + 128] = b_e2[tid + 128];
    {
        const float* adjrow = g_adjT + ((size_t)b * NN + (bid & (NN - 1))) * NN;
        #pragma unroll
        for (int p = 0; p < 4; p++) s_adj[tid + p * 128] = adjrow[tid + p * 128];
    }

    const uint32_t swb   = (uint32_t)(lane & 7);
    const uint32_t svB   = smem_to_u32(sV);
    const __half*  vbase = g_v16 + (size_t)b * NN * HH;

    // cp.async V constants: column chunk c = lane (fixed), rows warp+4p
    const uint32_t coff = (lane < 16) ? (uint32_t)(lane * 16)
                                      : (uint32_t)(272 + (lane - 16) * 16);
    const int csrc = lane * 8;            // halfs

    // build mapping: row ii = tid>>1, 128-half k-range kb
    const int ii = tid >> 1;
    const int kb = (tid & 1) * 128;
    const __half* vsrcS = sV + ii * VSTRIDE + ((tid & 1) ? VHALF2 : 0);
    const __half* usrc  = s_u16 + kb;
    char* adst = (char*)sA + ii * 512;
    const int sw = ii & 7;

    // ---- prologue: stage V(0), build A(0) ----
    {
        const __half* vg = vbase;
        #pragma unroll
        for (int p = 0; p < 16; p++) {
            int r = warp + p * 4;
            cp_async16(svB + (uint32_t)r * (VSTRIDE * 2) + coff, vg + (size_t)r * HH + csrc);
        }
        CP_COMMIT();
        CP_WAIT(0);
        __syncthreads();
        #pragma unroll
        for (int p = 0; p < 16; p++) {
            uint4 v = ((const uint4*)vsrcS)[p];
            uint4 u = ((const uint4*)usrc)[p];
            uint4 o;
            o.x = hrelu2(v.x, u.x);
            o.y = hrelu2(v.y, u.y);
            o.z = hrelu2(v.z, u.z);
            o.w = hrelu2(v.w, u.w);
            int c16 = (kb >> 3) + p;
            *(uint4*)(adst + ((c16 ^ sw) << 4)) = o;
        }
    }
    __syncthreads();

    float partial[16];
    #pragma unroll
    for (int c = 0; c < 16; c++) partial[c] = 0.0f;

    #pragma unroll 1
    for (int iter = 0; iter < 8; iter++) {
        // ---- stage V(iter+1) (fire and forget) ----
        if (iter < 7) {
            const __half* vg = vbase + (size_t)((iter + 1) * 64) * HH;
            #pragma unroll
            for (int p = 0; p < 16; p++) {
                int r = warp + p * 4;
                cp_async16(svB + (uint32_t)r * (VSTRIDE * 2) + coff, vg + (size_t)r * HH + csrc);
            }
            CP_COMMIT();
        }

        // ---- mma t-loop over A(iter): smem + W-frags (2-deep reg pipeline) ----
        const uint32_t rbase = smem_to_u32(sA) + (uint32_t)(lane & 15) * 512;
        float C[4][8][4];
        #pragma unroll
        for (int m = 0; m < 4; m++)
            #pragma unroll
            for (int j = 0; j < 8; j++)
                #pragma unroll
                for (int e = 0; e < 4; e++) C[m][j][e] = 0.0f;

        #pragma unroll 1
        for (int t = 0; t < 8; t++) {
            uint32_t a0[4][4], a1[4][4];
            uint32_t c0 = (uint32_t)(4 * t + hi4);
            #pragma unroll
            for (int m = 0; m < 4; m++) {
                uint32_t rb = rbase + (uint32_t)(m * 16) * 512;
                ldm4(a0[m], rb + (((c0)     ^ swb) << 4));
                ldm4(a1[m], rb + (((c0 + 2) ^ swb) << 4));
            }
            const uint4* wp = g_Wh + ((t * 32) + warp * 8) * 32 + lane;
            // 2-deep register pipeline of W fragments: wf[j+2] in flight
            uint4 wfA = wp[0];
            uint4 wfB = wp[32];
            #pragma unroll
            for (int j = 0; j < 8; j++) {
                uint4 wfN;
                if (j < 6) wfN = wp[(j + 2) * 32];
                #pragma unroll
                for (int m = 0; m < 4; m++) {
                    mma_f16(C[m][j], a0[m], wfA.x, wfA.y);
                    mma_f16(C[m][j], a1[m], wfA.z, wfA.w);
                }
                wfA = wfB;
                wfB = wfN;
            }
        }

        // ---- epilogue: bias + relu, adj-weight, accumulate over i ----
        #pragma unroll
        for (int m = 0; m < 4; m++) {
            float aw0 = s_adj[iter * 64 + m * 16 + rg];
            float aw1 = s_adj[iter * 64 + m * 16 + rg + 8];
            #pragma unroll
            for (int j = 0; j < 8; j++) {
                float bb0 = s_b2[warp * 64 + j * 8 + q * 2];
                float bb1 = s_b2[warp * 64 + j * 8 + q * 2 + 1];
                partial[j*2+0] += aw0 * fmaxf(C[m][j][0] + bb0, 0.0f)
                                + aw1 * fmaxf(C[m][j][2] + bb0, 0.0f);
                partial[j*2+1] += aw0 * fmaxf(C[m][j][1] + bb1, 0.0f)
                                + aw1 * fmaxf(C[m][j][3] + bb1, 0.0f);
            }
        }

        // ---- wait V(iter+1), rebuild A in place ----
        if (iter < 7) {
            CP_WAIT(0);
        }
        __syncthreads();   // A fully consumed by all warps + V arrival visible
        if (iter < 7) {
            #pragma unroll
            for (int p = 0; p < 16; p++) {
                uint4 v = ((const uint4*)vsrcS)[p];
                uint4 u = ((const uint4*)usrc)[p];
                uint4 o;
                o.x = hrelu2(v.x, u.x);
                o.y = hrelu2(v.y, u.y);
                o.z = hrelu2(v.z, u.z);
                o.w = hrelu2(v.w, u.w);
                int c16 = (kb >> 3) + p;
                *(uint4*)(adst + ((c16 ^ sw) << 4)) = o;
            }
            __syncthreads();   // A(iter+1) ready
        }
    }

    // ---- reduce over 8 row-groups (lanes stride 4); lanes 0-3 write ----
    #pragma unroll
    for (int c = 0; c < 16; c++) {
        float v = partial[c];
        v += __shfl_down_sync(0xffffffffu, v, 16);
        v += __shfl_down_sync(0xffffffffu, v, 8);
        v += __shfl_down_sync(0xffffffffu, v, 4);
        partial[c] = v;
    }
    if (lane < 4) {
        #pragma unroll
        for (int c = 0; c < 16; c++) {
            int col = warp * 64 + (c >> 1) * 8 + lane * 2 + (c & 1);
            g_agg[bid * HH + col] = partial[c];
        }
    }
}

// ---------------------------------------------------------------------------
// Kernel C: per-node MLP + log_softmax
// ---------------------------------------------------------------------------
__global__ __launch_bounds__(256, 4)
void tail_kernel(const float* __restrict__ x,
                 const float* __restrict__ W_n1, const float* __restrict__ b_n1,
                 const float* __restrict__ W_n2, const float* __restrict__ b_n2,
                 const float* __restrict__ W_o1, const float* __restrict__ b_o1,
                 const float* __restrict__ W_o,  const float* __restrict__ b_o,
                 float* __restrict__ out) {
    __shared__ float sA[8][256];
    __shared__ float sB[8][256];
    __shared__ float sx[8][4];

    const int row0 = blockIdx.x * 8;
    const int tid  = threadIdx.x;

    #pragma unroll
    for (int r = 0; r < 8; r++) sA[r][tid] = g_agg[(row0 + r) * HH + tid];
    if (tid < 32) sx[tid >> 2][tid & 3] = x[row0 * DD + tid];
    __syncthreads();

    {
        float acc[8];
        #pragma unroll
        for (int r = 0; r < 8; r++) acc[r] = b_n1[tid];
        #pragma unroll 4
        for (int k = 0; k < 256; k++) {
            float wv = W_n1[k * 256 + tid];
            #pragma unroll
            for (int r = 0; r < 8; r++) acc[r] += sA[r][k] * wv;
        }
        #pragma unroll
        for (int r = 0; r < 8; r++) sB[r][tid] = fmaxf(acc[r], 0.0f);
        __syncthreads();
    }
    {
        float acc[8];
        #pragma unroll
        for (int r = 0; r < 8; r++) acc[r] = b_n2[tid];
        #pragma unroll 4
        for (int k = 0; k < 256; k++) {
            float wv = W_n2[k * 256 + tid];
            #pragma unroll
            for (int r = 0; r < 8; r++) acc[r] += sB[r][k] * wv;
        }
        __syncthreads();
        #pragma unroll
        for (int r = 0; r < 8; r++) sA[r][tid] = fmaxf(acc[r], 0.0f);
        __syncthreads();
    }
    {
        float acc[8];
        #pragma unroll
        for (int r = 0; r < 8; r++) acc[r] = b_o1[tid];
        #pragma unroll
        for (int d = 0; d < 4; d++) {
            float wv = W_o1[d * 256 + tid];
            #pragma unroll
            for (int r = 0; r < 8; r++) acc[r] += sx[r][d] * wv;
        }
        #pragma unroll 4
        for (int k = 0; k < 256; k++) {
            float wv = W_o1[(4 + k) * 256 + tid];
            #pragma unroll
            for (int r = 0; r < 8; r++) acc[r] += sA[r][k] * wv;
        }
        __syncthreads();
        #pragma unroll
        for (int r = 0; r < 8; r++) sB[r][tid] = acc[r];
        __syncthreads();
    }
    if (tid < 32) {
        int r = tid >> 2, d = tid & 3;
        float acc = b_o[d];
        #pragma unroll 4
        for (int h = 0; h < 256; h++) acc += sB[r][h] * W_o[h * 4 + d];
        float m = acc;
        m = fmaxf(m, __shfl_xor_sync(0xffffffffu, m, 1));
        m = fmaxf(m, __shfl_xor_sync(0xffffffffu, m, 2));
        float e = expf(acc - m);
        float s = e;
        s += __shfl_xor_sync(0xffffffffu, s, 1);
        s += __shfl_xor_sync(0xffffffffu, s, 2);
        out[(row0 + r) * 4 + d] = acc - m - logf(s);
    }
}

// ---------------------------------------------------------------------------
// Launch
// ---------------------------------------------------------------------------
extern "C" void kernel_launch(void* const* d_in, const int* in_sizes, int n_in,
                              void* d_out, int out_size) {
    const float* x    = (const float*)d_in[0];
    const float* adj  = (const float*)d_in[1];
    const float* W_e1 = (const float*)d_in[2];
    const float* b_e1 = (const float*)d_in[3];
    const float* W_e2 = (const float*)d_in[4];
    const float* b_e2 = (const float*)d_in[5];
    const float* W_n1 = (const float*)d_in[6];
    const float* b_n1 = (const float*)d_in[7];
    const float* W_n2 = (const float*)d_in[8];
    const float* b_n2 = (const float*)d_in[9];
    const float* W_o1 = (const float*)d_in[10];
    const float* b_o1 = (const float*)d_in[11];
    const float* W_o  = (const float*)d_in[12];
    const float* b_o  = (const float*)d_in[13];
    float* out = (float*)d_out;

    prep_uv_kernel<<<(BB * NN * HH) / 256, 256>>>(x, W_e1, b_e1);
    wfrag_kernel<<<32, 256>>>(W_e2);
    adjT_kernel<<<dim3(16, 16, 4), dim3(32, 32)>>>(adj);
    edge_mma_kernel<<<BB * NN, 128>>>(b_e2);
    tail_kernel<<<(BB * NN) / 8, 256>>>(x, W_n1, b_n1, W_n2, b_n2,
                                        W_o1, b_o1, W_o, b_o, out);
}

// round 12
// speedup vs baseline: 2.2227x; 1.0193x over previous
#include <cuda_runtime.h>
#include <cuda_bf16.h>
#include <cuda_fp16.h>
#include <cstdint>
#include <math.h>

#define BB 4
#define NN 512
#define DD 4
#define HH 256

// ---------------------------------------------------------------------------
// Device scratch (allocation-free rule)
// ---------------------------------------------------------------------------
__device__ __align__(16) __half g_u16[BB * NN * HH];  // x[b,j]@W_e1[0:4]        (fp16)
__device__ __align__(16) __half g_v16[BB * NN * HH];  // x[b,i]@W_e1[4:8]+b_e1   (fp16)
__device__ __align__(16) float  g_agg[BB * NN * HH];
// W_e2 fp16 mma B-fragments, two k-steps per uint4:
// [t(8)][g(32)][lane(32)] -> uint4{ b0(s=2t), b1(s=2t), b0(s=2t+1), b1(s=2t+1) }
__device__ __align__(16) uint4 g_Wh[8 * 32 * 32];

// ---------------------------------------------------------------------------
// PTX wrappers (baseline sm_80-class; compile clean for compute_103)
// ---------------------------------------------------------------------------
__device__ __forceinline__ uint32_t smem_to_u32(const void* p) {
    uint32_t a;
    asm("{ .reg .u64 t; cvta.to.shared.u64 t, %1; cvt.u32.u64 %0, t; }" : "=r"(a) : "l"(p));
    return a;
}

__device__ __forceinline__ void ldm4(uint32_t r[4], uint32_t addr) {
    asm volatile("ldmatrix.sync.aligned.m8n8.x4.shared.b16 {%0,%1,%2,%3}, [%4];"
                 : "=r"(r[0]), "=r"(r[1]), "=r"(r[2]), "=r"(r[3]) : "r"(addr));
}

__device__ __forceinline__ void mma_f16(float c[4], const uint32_t a[4],
                                        uint32_t b0, uint32_t b1) {
    asm volatile(
        "mma.sync.aligned.m16n8k16.row.col.f32.f16.f16.f32 "
        "{%0,%1,%2,%3}, {%4,%5,%6,%7}, {%8,%9}, {%0,%1,%2,%3};"
        : "+f"(c[0]), "+f"(c[1]), "+f"(c[2]), "+f"(c[3])
        : "r"(a[0]), "r"(a[1]), "r"(a[2]), "r"(a[3]), "r"(b0), "r"(b1));
}

__device__ __forceinline__ uint32_t pack_h2(float a, float b) {
    __half2 h = __floats2half2_rn(a, b);
    return *(uint32_t*)&h;
}

__device__ __forceinline__ uint32_t hrelu2(uint32_t va, uint32_t ua) {
    __half2 s = __hadd2(*(const __half2*)&va, *(const __half2*)&ua);
    __half2 z = __float2half2_rn(0.0f);
    __half2 r = __hmax2(s, z);
    return *(uint32_t*)&r;
}

__device__ __forceinline__ void cp_async16(uint32_t dst, const void* src) {
    asm volatile("cp.async.cg.shared.global [%0], [%1], 16;" :: "r"(dst), "l"(src));
}
#define CP_COMMIT() asm volatile("cp.async.commit_group;" ::: "memory")
#define CP_WAIT(N)  asm volatile("cp.async.wait_group %0;" :: "n"(N) : "memory")

// ---------------------------------------------------------------------------
// Kernel A: u, v in fp16
// ---------------------------------------------------------------------------
__global__ void prep_uv_kernel(const float* __restrict__ x,
                               const float* __restrict__ W_e1,
                               const float* __restrict__ b_e1) {
    int idx = blockIdx.x * blockDim.x + threadIdx.x;
    if (idx >= BB * NN * HH) return;
    int h  = idx & (HH - 1);
    int bn = idx >> 8;
    const float* xr = x + bn * DD;
    float su = 0.0f;
    float sv = b_e1[h];
    #pragma unroll
    for (int d = 0; d < DD; d++) {
        float xv = xr[d];
        su += xv * W_e1[d * HH + h];
        sv += xv * W_e1[(DD + d) * HH + h];
    }
    g_u16[idx] = __float2half_rn(su);
    g_v16[idx] = __float2half_rn(sv);
}

// ---------------------------------------------------------------------------
// Kernel W: pack W_e2 (fp16) into mma B-fragment layout, 2 k-steps per uint4
// ---------------------------------------------------------------------------
__global__ void wfrag_kernel(const float* __restrict__ W_e2) {
    int idx = blockIdx.x * blockDim.x + threadIdx.x;   // 8192
    if (idx >= 8 * 32 * 32) return;
    int lane = idx & 31;
    int g    = (idx >> 5) & 31;
    int t    = idx >> 10;
    int n  = g * 8 + (lane >> 2);
    int q  = lane & 3;
    int k0 = (2 * t) * 16 + q * 2;
    int k1 = (2 * t + 1) * 16 + q * 2;

    uint4 o;
    o.x = pack_h2(W_e2[(k0)     * HH + n], W_e2[(k0 + 1) * HH + n]);
    o.y = pack_h2(W_e2[(k0 + 8) * HH + n], W_e2[(k0 + 9) * HH + n]);
    o.z = pack_h2(W_e2[(k1)     * HH + n], W_e2[(k1 + 1) * HH + n]);
    o.w = pack_h2(W_e2[(k1 + 8) * HH + n], W_e2[(k1 + 9) * HH + n]);
    g_Wh[idx] = o;
}

// ---------------------------------------------------------------------------
// Kernel E: per (b,j) edge GEMM, fused bias+relu+adj-weighted i-reduction.
// 4 warps; warp tile 64(M) x 64(N). A double-buffered: next i-tile's raw v is
// cp.async'd directly into the other A buffer in final swizzled layout; the
// relu(u+v) transform runs IN PLACE inside the t-loop (t=4..7), per-warp
// self-contained (warp transforms the rows it staged -> __syncwarp only).
// One __syncthreads per iter. mma t-loop: smem + L1 W-frags.
// ---------------------------------------------------------------------------
__global__ __launch_bounds__(128, 2)
void edge_mma_kernel(const float* __restrict__ adj, const float* __restrict__ b_e2) {
    __shared__ __align__(16) __half s_u16[HH];
    __shared__ float s_b2[HH];
    __shared__ float s_adj[NN];
    __shared__ __align__(16) __half sA[2 * 64 * 256];   // two 32KB buffers

    const int bid  = blockIdx.x;          // b*512 + j
    const int b    = bid >> 9;
    const int jj   = bid & (NN - 1);
    const int tid  = threadIdx.x;
    const int warp = tid >> 5;            // owns cols [warp*64, +64)
    const int lane = tid & 31;
    const int rg   = lane >> 2;
    const int q    = lane & 3;
    const int hi4  = lane >> 4;

    const uint32_t aB    = smem_to_u32(sA);
    const __half*  vbase = g_v16 + (size_t)b * NN * HH;

    // transform constants: warp transforms rows it staged
    const int tr_r = warp * 16 + (lane & 15);            // row within tile
    const int tr_h = lane >> 4;                          // chunk half: 0 or 1
    const uint32_t tr_sw = (uint32_t)(tr_r & 7);

    // ---- prologue: stage V(0) -> buf0, load u/b2/adj, transform buf0 ----
    {
        #pragma unroll
        for (int p = 0; p < 16; p++) {
            int r = warp * 16 + p;
            cp_async16(aB + (uint32_t)r * 512 + ((uint32_t)(lane ^ (r & 7)) << 4),
                       vbase + (size_t)r * HH + lane * 8);
        }
        CP_COMMIT();
    }
    if (tid < 32)
        ((uint4*)s_u16)[tid] = ((const uint4*)(g_u16 + (size_t)bid * HH))[tid];
    s_b2[tid]       = b_e2[tid];
    s_b2[tid + 128] = b_e2[tid + 128];
    {
        // strided direct adj column load: adj[b][i][jj]
        #pragma unroll
        for (int p = 0; p < 4; p++) {
            int i = p * 128 + tid;
            s_adj[i] = adj[((size_t)b * NN + i) * NN + jj];
        }
    }
    CP_WAIT(0);
    __syncthreads();    // u + staged v(0) visible to all
    {
        char* buf0 = (char*)sA;
        #pragma unroll
        for (int p = 0; p < 16; p++) {
            int c16 = tr_h * 16 + p;
            uint32_t off = (uint32_t)tr_r * 512 + ((uint32_t)(c16 ^ tr_sw) << 4);
            uint4 v = *(const uint4*)(buf0 + off);
            uint4 u = *(const uint4*)((const char*)s_u16 + c16 * 16);
            uint4 o;
            o.x = hrelu2(v.x, u.x);
            o.y = hrelu2(v.y, u.y);
            o.z = hrelu2(v.z, u.z);
            o.w = hrelu2(v.w, u.w);
            *(uint4*)(buf0 + off) = o;
        }
    }
    __syncthreads();    // A(0) ready

    float partial[16];
    #pragma unroll
    for (int c = 0; c < 16; c++) partial[c] = 0.0f;

    #pragma unroll 1
    for (int iter = 0; iter < 8; iter++) {
        const int cur = iter & 1;
        const int nxt = cur ^ 1;
        char* bufN = (char*)sA + nxt * 32768;
        const uint32_t bufNB = aB + (uint32_t)nxt * 32768;

        // ---- stage raw V(iter+1) into bufN (fire and forget) ----
        if (iter < 7) {
            const __half* vg = vbase + (size_t)((iter + 1) * 64) * HH;
            #pragma unroll
            for (int p = 0; p < 16; p++) {
                int r = warp * 16 + p;
                cp_async16(bufNB + (uint32_t)r * 512 + ((uint32_t)(lane ^ (r & 7)) << 4),
                           vg + (size_t)r * HH + lane * 8);
            }
            CP_COMMIT();
        }

        // ---- mma t-loop over A(cur); transform bufN in place at t=4..7 ----
        const uint32_t rbase = aB + (uint32_t)cur * 32768 + (uint32_t)(lane & 15) * 512;
        const uint32_t swb   = (uint32_t)(lane & 7);
        float C[4][8][4];
        #pragma unroll
        for (int m = 0; m < 4; m++)
            #pragma unroll
            for (int j = 0; j < 8; j++)
                #pragma unroll
                for (int e = 0; e < 4; e++) C[m][j][e] = 0.0f;

        #pragma unroll 1
        for (int t = 0; t < 8; t++) {
            uint32_t a0[4][4], a1[4][4];
            uint32_t c0 = (uint32_t)(4 * t + hi4);
            #pragma unroll
            for (int m = 0; m < 4; m++) {
                uint32_t rb = rbase + (uint32_t)(m * 16) * 512;
                ldm4(a0[m], rb + (((c0)     ^ swb) << 4));
                ldm4(a1[m], rb + (((c0 + 2) ^ swb) << 4));
            }

            // in-place transform of next tile, hidden under mma issue
            if (iter < 7 && t >= 4) {
                if (t == 4) { CP_WAIT(0); __syncwarp(); }
                #pragma unroll
                for (int p = 0; p < 4; p++) {
                    int c16 = tr_h * 16 + (t - 4) * 4 + p;
                    uint32_t off = (uint32_t)tr_r * 512 + ((uint32_t)(c16 ^ tr_sw) << 4);
                    uint4 v = *(const uint4*)(bufN + off);
                    uint4 u = *(const uint4*)((const char*)s_u16 + c16 * 16);
                    uint4 o;
                    o.x = hrelu2(v.x, u.x);
                    o.y = hrelu2(v.y, u.y);
                    o.z = hrelu2(v.z, u.z);
                    o.w = hrelu2(v.w, u.w);
                    *(uint4*)(bufN + off) = o;
                }
            }

            const uint4* wp = g_Wh + ((t * 32) + warp * 8) * 32 + lane;
            uint4 wfA = wp[0];
            uint4 wfB = wp[32];
            #pragma unroll
            for (int j = 0; j < 8; j++) {
                uint4 wfN;
                if (j < 6) wfN = wp[(j + 2) * 32];
                #pragma unroll
                for (int m = 0; m < 4; m++) {
                    mma_f16(C[m][j], a0[m], wfA.x, wfA.y);
                    mma_f16(C[m][j], a1[m], wfA.z, wfA.w);
                }
                wfA = wfB;
                wfB = wfN;
            }
        }

        // ---- epilogue: bias + relu, adj-weight, accumulate over i ----
        #pragma unroll
        for (int m = 0; m < 4; m++) {
            float aw0 = s_adj[iter * 64 + m * 16 + rg];
            float aw1 = s_adj[iter * 64 + m * 16 + rg + 8];
            #pragma unroll
            for (int j = 0; j < 8; j++) {
                float bb0 = s_b2[warp * 64 + j * 8 + q * 2];
                float bb1 = s_b2[warp * 64 + j * 8 + q * 2 + 1];
                partial[j*2+0] += aw0 * fmaxf(C[m][j][0] + bb0, 0.0f)
                                + aw1 * fmaxf(C[m][j][2] + bb0, 0.0f);
                partial[j*2+1] += aw0 * fmaxf(C[m][j][1] + bb1, 0.0f)
                                + aw1 * fmaxf(C[m][j][3] + bb1, 0.0f);
            }
        }

        // single barrier per iter: transform STS (all warps) visible before
        // next iter's ldmatrix; cur buffer fully consumed before its refill.
        __syncthreads();
    }

    // ---- reduce over 8 row-groups (lanes stride 4); lanes 0-3 write ----
    #pragma unroll
    for (int c = 0; c < 16; c++) {
        float v = partial[c];
        v += __shfl_down_sync(0xffffffffu, v, 16);
        v += __shfl_down_sync(0xffffffffu, v, 8);
        v += __shfl_down_sync(0xffffffffu, v, 4);
        partial[c] = v;
    }
    if (lane < 4) {
        #pragma unroll
        for (int c = 0; c < 16; c++) {
            int col = warp * 64 + (c >> 1) * 8 + lane * 2 + (c & 1);
            g_agg[bid * HH + col] = partial[c];
        }
    }
}

// ---------------------------------------------------------------------------
// Kernel C: per-node MLP + log_softmax
// ---------------------------------------------------------------------------
__global__ __launch_bounds__(256, 4)
void tail_kernel(const float* __restrict__ x,
                 const float* __restrict__ W_n1, const float* __restrict__ b_n1,
                 const float* __restrict__ W_n2, const float* __restrict__ b_n2,
                 const float* __restrict__ W_o1, const float* __restrict__ b_o1,
                 const float* __restrict__ W_o,  const float* __restrict__ b_o,
                 float* __restrict__ out) {
    __shared__ float sA[8][256];
    __shared__ float sB[8][256];
    __shared__ float sx[8][4];

    const int row0 = blockIdx.x * 8;
    const int tid  = threadIdx.x;

    #pragma unroll
    for (int r = 0; r < 8; r++) sA[r][tid] = g_agg[(row0 + r) * HH + tid];
    if (tid < 32) sx[tid >> 2][tid & 3] = x[row0 * DD + tid];
    __syncthreads();

    {
        float acc[8];
        #pragma unroll
        for (int r = 0; r < 8; r++) acc[r] = b_n1[tid];
        #pragma unroll 4
        for (int k = 0; k < 256; k++) {
            float wv = W_n1[k * 256 + tid];
            #pragma unroll
            for (int r = 0; r < 8; r++) acc[r] += sA[r][k] * wv;
        }
        #pragma unroll
        for (int r = 0; r < 8; r++) sB[r][tid] = fmaxf(acc[r], 0.0f);
        __syncthreads();
    }
    {
        float acc[8];
        #pragma unroll
        for (int r = 0; r < 8; r++) acc[r] = b_n2[tid];
        #pragma unroll 4
        for (int k = 0; k < 256; k++) {
            float wv = W_n2[k * 256 + tid];
            #pragma unroll
            for (int r = 0; r < 8; r++) acc[r] += sB[r][k] * wv;
        }
        __syncthreads();
        #pragma unroll
        for (int r = 0; r < 8; r++) sA[r][tid] = fmaxf(acc[r], 0.0f);
        __syncthreads();
    }
    {
        float acc[8];
        #pragma unroll
        for (int r = 0; r < 8; r++) acc[r] = b_o1[tid];
        #pragma unroll
        for (int d = 0; d < 4; d++) {
            float wv = W_o1[d * 256 + tid];
            #pragma unroll
            for (int r = 0; r < 8; r++) acc[r] += sx[r][d] * wv;
        }
        #pragma unroll 4
        for (int k = 0; k < 256; k++) {
            float wv = W_o1[(4 + k) * 256 + tid];
            #pragma unroll
            for (int r = 0; r < 8; r++) acc[r] += sA[r][k] * wv;
        }
        __syncthreads();
        #pragma unroll
        for (int r = 0; r < 8; r++) sB[r][tid] = acc[r];
        __syncthreads();
    }
    if (tid < 32) {
        int r = tid >> 2, d = tid & 3;
        float acc = b_o[d];
        #pragma unroll 4
        for (int h = 0; h < 256; h++) acc += sB[r][h] * W_o[h * 4 + d];
        float m = acc;
        m = fmaxf(m, __shfl_xor_sync(0xffffffffu, m, 1));
        m = fmaxf(m, __shfl_xor_sync(0xffffffffu, m, 2));
        float e = expf(acc - m);
        float s = e;
        s += __shfl_xor_sync(0xffffffffu, s, 1);
        s += __shfl_xor_sync(0xffffffffu, s, 2);
        out[(row0 + r) * 4 + d] = acc - m - logf(s);
    }
}

// ---------------------------------------------------------------------------
// Launch
// ---------------------------------------------------------------------------
extern "C" void kernel_launch(void* const* d_in, const int* in_sizes, int n_in,
                              void* d_out, int out_size) {
    const float* x    = (const float*)d_in[0];
    const float* adj  = (const float*)d_in[1];
    const float* W_e1 = (const float*)d_in[2];
    const float* b_e1 = (const float*)d_in[3];
    const float* W_e2 = (const float*)d_in[4];
    const float* b_e2 = (const float*)d_in[5];
    const float* W_n1 = (const float*)d_in[6];
    const float* b_n1 = (const float*)d_in[7];
    const float* W_n2 = (const float*)d_in[8];
    const float* b_n2 = (const float*)d_in[9];
    const float* W_o1 = (const float*)d_in[10];
    const float* b_o1 = (const float*)d_in[11];
    const float* W_o  = (const float*)d_in[12];
    const float* b_o  = (const float*)d_in[13];
    float* out = (float*)d_out;

    prep_uv_kernel<<<(BB * NN * HH) / 256, 256>>>(x, W_e1, b_e1);
    wfrag_kernel<<<32, 256>>>(W_e2);
    edge_mma_kernel<<<BB * NN, 128>>>(adj, b_e2);
    tail_kernel<<<(BB * NN) / 8, 256>>>(x, W_n1, b_n1, W_n2, b_n2,
                                        W_o1, b_o1, W_o, b_o, out);
}

// round 13
// speedup vs baseline: 2.2238x; 1.0005x over previous
#include <cuda_runtime.h>
#include <cuda_bf16.h>
#include <cuda_fp16.h>
#include <cstdint>
#include <math.h>

#define BB 4
#define NN 512
#define DD 4
#define HH 256

// ---------------------------------------------------------------------------
// Device scratch (allocation-free rule)
// ---------------------------------------------------------------------------
__device__ __align__(16) __half g_u16[BB * NN * HH];  // x[b,j]@W_e1[0:4]        (fp16)
__device__ __align__(16) __half g_v16[BB * NN * HH];  // x[b,i]@W_e1[4:8]+b_e1   (fp16)
__device__ __align__(16) float  g_agg[BB * NN * HH];
// W_e2 fp16 mma B-fragments, two k-steps per uint4:
// [t(8)][g(32)][lane(32)] -> uint4{ b0(s=2t), b1(s=2t), b0(s=2t+1), b1(s=2t+1) }
__device__ __align__(16) uint4 g_Wh[8 * 32 * 32];

// ---------------------------------------------------------------------------
// PTX wrappers (baseline sm_80-class; compile clean for compute_103)
// ---------------------------------------------------------------------------
__device__ __forceinline__ uint32_t smem_to_u32(const void* p) {
    uint32_t a;
    asm("{ .reg .u64 t; cvta.to.shared.u64 t, %1; cvt.u32.u64 %0, t; }" : "=r"(a) : "l"(p));
    return a;
}

__device__ __forceinline__ void ldm4(uint32_t r[4], uint32_t addr) {
    asm volatile("ldmatrix.sync.aligned.m8n8.x4.shared.b16 {%0,%1,%2,%3}, [%4];"
                 : "=r"(r[0]), "=r"(r[1]), "=r"(r[2]), "=r"(r[3]) : "r"(addr));
}

__device__ __forceinline__ void mma_f16(float c[4], const uint32_t a[4],
                                        uint32_t b0, uint32_t b1) {
    asm volatile(
        "mma.sync.aligned.m16n8k16.row.col.f32.f16.f16.f32 "
        "{%0,%1,%2,%3}, {%4,%5,%6,%7}, {%8,%9}, {%0,%1,%2,%3};"
        : "+f"(c[0]), "+f"(c[1]), "+f"(c[2]), "+f"(c[3])
        : "r"(a[0]), "r"(a[1]), "r"(a[2]), "r"(a[3]), "r"(b0), "r"(b1));
}

__device__ __forceinline__ uint32_t pack_h2(float a, float b) {
    __half2 h = __floats2half2_rn(a, b);
    return *(uint32_t*)&h;
}

__device__ __forceinline__ uint32_t hrelu2(uint32_t va, uint32_t ua) {
    __half2 s = __hadd2(*(const __half2*)&va, *(const __half2*)&ua);
    __half2 z = __float2half2_rn(0.0f);
    __half2 r = __hmax2(s, z);
    return *(uint32_t*)&r;
}

__device__ __forceinline__ void cp_async16(uint32_t dst, const void* src) {
    asm volatile("cp.async.cg.shared.global [%0], [%1], 16;" :: "r"(dst), "l"(src));
}
#define CP_COMMIT() asm volatile("cp.async.commit_group;" ::: "memory")
#define CP_WAIT(N)  asm volatile("cp.async.wait_group %0;" :: "n"(N) : "memory")

// ---------------------------------------------------------------------------
// Kernel A: u, v in fp16
// ---------------------------------------------------------------------------
__global__ void prep_uv_kernel(const float* __restrict__ x,
                               const float* __restrict__ W_e1,
                               const float* __restrict__ b_e1) {
    int idx = blockIdx.x * blockDim.x + threadIdx.x;
    if (idx >= BB * NN * HH) return;
    int h  = idx & (HH - 1);
    int bn = idx >> 8;
    const float* xr = x + bn * DD;
    float su = 0.0f;
    float sv = b_e1[h];
    #pragma unroll
    for (int d = 0; d < DD; d++) {
        float xv = xr[d];
        su += xv * W_e1[d * HH + h];
        sv += xv * W_e1[(DD + d) * HH + h];
    }
    g_u16[idx] = __float2half_rn(su);
    g_v16[idx] = __float2half_rn(sv);
}

// ---------------------------------------------------------------------------
// Kernel W: pack W_e2 (fp16) into mma B-fragment layout, 2 k-steps per uint4
// ---------------------------------------------------------------------------
__global__ void wfrag_kernel(const float* __restrict__ W_e2) {
    int idx = blockIdx.x * blockDim.x + threadIdx.x;   // 8192
    if (idx >= 8 * 32 * 32) return;
    int lane = idx & 31;
    int g    = (idx >> 5) & 31;
    int t    = idx >> 10;
    int n  = g * 8 + (lane >> 2);
    int q  = lane & 3;
    int k0 = (2 * t) * 16 + q * 2;
    int k1 = (2 * t + 1) * 16 + q * 2;

    uint4 o;
    o.x = pack_h2(W_e2[(k0)     * HH + n], W_e2[(k0 + 1) * HH + n]);
    o.y = pack_h2(W_e2[(k0 + 8) * HH + n], W_e2[(k0 + 9) * HH + n]);
    o.z = pack_h2(W_e2[(k1)     * HH + n], W_e2[(k1 + 1) * HH + n]);
    o.w = pack_h2(W_e2[(k1 + 8) * HH + n], W_e2[(k1 + 9) * HH + n]);
    g_Wh[idx] = o;
}

// ---------------------------------------------------------------------------
// Kernel E: per (b,j) edge GEMM, fused bias+relu+adj-weighted i-reduction.
// 4 warps; warp tile 64(M) x 64(N). A double-buffered: next i-tile's raw v is
// cp.async'd directly into the other A buffer in final swizzled layout; the
// relu(u+v) transform runs IN PLACE inside the t-loop (t=4..7), per-warp
// self-contained (warp transforms the rows it staged -> __syncwarp only).
// One __syncthreads per iter. mma t-loop: smem + L1 W-frags.
// ---------------------------------------------------------------------------
__global__ __launch_bounds__(128, 2)
void edge_mma_kernel(const float* __restrict__ adj, const float* __restrict__ b_e2) {
    __shared__ __align__(16) __half s_u16[HH];
    __shared__ float s_b2[HH];
    __shared__ float s_adj[NN];
    __shared__ __align__(16) __half sA[2 * 64 * 256];   // two 32KB buffers

    const int bid  = blockIdx.x;          // b*512 + j
    const int b    = bid >> 9;
    const int jj   = bid & (NN - 1);
    const int tid  = threadIdx.x;
    const int warp = tid >> 5;            // owns cols [warp*64, +64)
    const int lane = tid & 31;
    const int rg   = lane >> 2;
    const int q    = lane & 3;
    const int hi4  = lane >> 4;

    const uint32_t aB    = smem_to_u32(sA);
    const __half*  vbase = g_v16 + (size_t)b * NN * HH;

    // transform constants: warp transforms rows it staged
    const int tr_r = warp * 16 + (lane & 15);            // row within tile
    const int tr_h = lane >> 4;                          // chunk half: 0 or 1
    const uint32_t tr_sw = (uint32_t)(tr_r & 7);

    // ---- prologue: stage V(0) -> buf0, load u/b2/adj, transform buf0 ----
    {
        #pragma unroll
        for (int p = 0; p < 16; p++) {
            int r = warp * 16 + p;
            cp_async16(aB + (uint32_t)r * 512 + ((uint32_t)(lane ^ (r & 7)) << 4),
                       vbase + (size_t)r * HH + lane * 8);
        }
        CP_COMMIT();
    }
    if (tid < 32)
        ((uint4*)s_u16)[tid] = ((const uint4*)(g_u16 + (size_t)bid * HH))[tid];
    s_b2[tid]       = b_e2[tid];
    s_b2[tid + 128] = b_e2[tid + 128];
    {
        // strided direct adj column load: adj[b][i][jj]
        #pragma unroll
        for (int p = 0; p < 4; p++) {
            int i = p * 128 + tid;
            s_adj[i] = adj[((size_t)b * NN + i) * NN + jj];
        }
    }
    CP_WAIT(0);
    __syncthreads();    // u + staged v(0) visible to all
    {
        char* buf0 = (char*)sA;
        #pragma unroll
        for (int p = 0; p < 16; p++) {
            int c16 = tr_h * 16 + p;
            uint32_t off = (uint32_t)tr_r * 512 + ((uint32_t)(c16 ^ tr_sw) << 4);
            uint4 v = *(const uint4*)(buf0 + off);
            uint4 u = *(const uint4*)((const char*)s_u16 + c16 * 16);
            uint4 o;
            o.x = hrelu2(v.x, u.x);
            o.y = hrelu2(v.y, u.y);
            o.z = hrelu2(v.z, u.z);
            o.w = hrelu2(v.w, u.w);
            *(uint4*)(buf0 + off) = o;
        }
    }
    __syncthreads();    // A(0) ready

    float partial[16];
    #pragma unroll
    for (int c = 0; c < 16; c++) partial[c] = 0.0f;

    #pragma unroll 1
    for (int iter = 0; iter < 8; iter++) {
        const int cur = iter & 1;
        const int nxt = cur ^ 1;
        char* bufN = (char*)sA + nxt * 32768;
        const uint32_t bufNB = aB + (uint32_t)nxt * 32768;

        // ---- stage raw V(iter+1) into bufN (fire and forget) ----
        if (iter < 7) {
            const __half* vg = vbase + (size_t)((iter + 1) * 64) * HH;
            #pragma unroll
            for (int p = 0; p < 16; p++) {
                int r = warp * 16 + p;
                cp_async16(bufNB + (uint32_t)r * 512 + ((uint32_t)(lane ^ (r & 7)) << 4),
                           vg + (size_t)r * HH + lane * 8);
            }
            CP_COMMIT();
        }

        // ---- mma t-loop over A(cur); transform bufN in place at t=4..7 ----
        const uint32_t rbase = aB + (uint32_t)cur * 32768 + (uint32_t)(lane & 15) * 512;
        const uint32_t swb   = (uint32_t)(lane & 7);
        float C[4][8][4];
        #pragma unroll
        for (int m = 0; m < 4; m++)
            #pragma unroll
            for (int j = 0; j < 8; j++)
                #pragma unroll
                for (int e = 0; e < 4; e++) C[m][j][e] = 0.0f;

        #pragma unroll 1
        for (int t = 0; t < 8; t++) {
            uint32_t a0[4][4], a1[4][4];
            uint32_t c0 = (uint32_t)(4 * t + hi4);
            #pragma unroll
            for (int m = 0; m < 4; m++) {
                uint32_t rb = rbase + (uint32_t)(m * 16) * 512;
                ldm4(a0[m], rb + (((c0)     ^ swb) << 4));
                ldm4(a1[m], rb + (((c0 + 2) ^ swb) << 4));
            }

            // in-place transform of next tile, hidden under mma issue
            if (iter < 7 && t >= 4) {
                if (t == 4) { CP_WAIT(0); __syncwarp(); }
                #pragma unroll
                for (int p = 0; p < 4; p++) {
                    int c16 = tr_h * 16 + (t - 4) * 4 + p;
                    uint32_t off = (uint32_t)tr_r * 512 + ((uint32_t)(c16 ^ tr_sw) << 4);
                    uint4 v = *(const uint4*)(bufN + off);
                    uint4 u = *(const uint4*)((const char*)s_u16 + c16 * 16);
                    uint4 o;
                    o.x = hrelu2(v.x, u.x);
                    o.y = hrelu2(v.y, u.y);
                    o.z = hrelu2(v.z, u.z);
                    o.w = hrelu2(v.w, u.w);
                    *(uint4*)(bufN + off) = o;
                }
            }

            const uint4* wp = g_Wh + ((t * 32) + warp * 8) * 32 + lane;
            uint4 wfA = wp[0];
            uint4 wfB = wp[32];
            #pragma unroll
            for (int j = 0; j < 8; j++) {
                uint4 wfN;
                if (j < 6) wfN = wp[(j + 2) * 32];
                #pragma unroll
                for (int m = 0; m < 4; m++) {
                    mma_f16(C[m][j], a0[m], wfA.x, wfA.y);
                    mma_f16(C[m][j], a1[m], wfA.z, wfA.w);
                }
                wfA = wfB;
                wfB = wfN;
            }
        }

        // ---- epilogue: bias + relu, adj-weight, accumulate over i ----
        #pragma unroll
        for (int m = 0; m < 4; m++) {
            float aw0 = s_adj[iter * 64 + m * 16 + rg];
            float aw1 = s_adj[iter * 64 + m * 16 + rg + 8];
            #pragma unroll
            for (int j = 0; j < 8; j++) {
                float bb0 = s_b2[warp * 64 + j * 8 + q * 2];
                float bb1 = s_b2[warp * 64 + j * 8 + q * 2 + 1];
                partial[j*2+0] += aw0 * fmaxf(C[m][j][0] + bb0, 0.0f)
                                + aw1 * fmaxf(C[m][j][2] + bb0, 0.0f);
                partial[j*2+1] += aw0 * fmaxf(C[m][j][1] + bb1, 0.0f)
                                + aw1 * fmaxf(C[m][j][3] + bb1, 0.0f);
            }
        }

        // single barrier per iter: transform STS (all warps) visible before
        // next iter's ldmatrix; cur buffer fully consumed before its refill.
        __syncthreads();
    }

    // ---- reduce over 8 row-groups (lanes stride 4); lanes 0-3 write ----
    #pragma unroll
    for (int c = 0; c < 16; c++) {
        float v = partial[c];
        v += __shfl_down_sync(0xffffffffu, v, 16);
        v += __shfl_down_sync(0xffffffffu, v, 8);
        v += __shfl_down_sync(0xffffffffu, v, 4);
        partial[c] = v;
    }
    if (lane < 4) {
        #pragma unroll
        for (int c = 0; c < 16; c++) {
            int col = warp * 64 + (c >> 1) * 8 + lane * 2 + (c & 1);
            g_agg[bid * HH + col] = partial[c];
        }
    }
}

// ---------------------------------------------------------------------------
// Kernel C: per-node MLP + log_softmax
// ---------------------------------------------------------------------------
__global__ __launch_bounds__(256, 4)
void tail_kernel(const float* __restrict__ x,
                 const float* __restrict__ W_n1, const float* __restrict__ b_n1,
                 const float* __restrict__ W_n2, const float* __restrict__ b_n2,
                 const float* __restrict__ W_o1, const float* __restrict__ b_o1,
                 const float* __restrict__ W_o,  const float* __restrict__ b_o,
                 float* __restrict__ out) {
    __shared__ float sA[8][256];
    __shared__ float sB[8][256];
    __shared__ float sx[8][4];

    const int row0 = blockIdx.x * 8;
    const int tid  = threadIdx.x;

    #pragma unroll
    for (int r = 0; r < 8; r++) sA[r][tid] = g_agg[(row0 + r) * HH + tid];
    if (tid < 32) sx[tid >> 2][tid & 3] = x[row0 * DD + tid];
    __syncthreads();

    {
        float acc[8];
        #pragma unroll
        for (int r = 0; r < 8; r++) acc[r] = b_n1[tid];
        #pragma unroll 4
        for (int k = 0; k < 256; k++) {
            float wv = W_n1[k * 256 + tid];
            #pragma unroll
            for (int r = 0; r < 8; r++) acc[r] += sA[r][k] * wv;
        }
        #pragma unroll
        for (int r = 0; r < 8; r++) sB[r][tid] = fmaxf(acc[r], 0.0f);
        __syncthreads();
    }
    {
        float acc[8];
        #pragma unroll
        for (int r = 0; r < 8; r++) acc[r] = b_n2[tid];
        #pragma unroll 4
        for (int k = 0; k < 256; k++) {
            float wv = W_n2[k * 256 + tid];
            #pragma unroll
            for (int r = 0; r < 8; r++) acc[r] += sB[r][k] * wv;
        }
        __syncthreads();
        #pragma unroll
        for (int r = 0; r < 8; r++) sA[r][tid] = fmaxf(acc[r], 0.0f);
        __syncthreads();
    }
    {
        float acc[8];
        #pragma unroll
        for (int r = 0; r < 8; r++) acc[r] = b_o1[tid];
        #pragma unroll
        for (int d = 0; d < 4; d++) {
            float wv = W_o1[d * 256 + tid];
            #pragma unroll
            for (int r = 0; r < 8; r++) acc[r] += sx[r][d] * wv;
        }
        #pragma unroll 4
        for (int k = 0; k < 256; k++) {
            float wv = W_o1[(4 + k) * 256 + tid];
            #pragma unroll
            for (int r = 0; r < 8; r++) acc[r] += sA[r][k] * wv;
        }
        __syncthreads();
        #pragma unroll
        for (int r = 0; r < 8; r++) sB[r][tid] = acc[r];
        __syncthreads();
    }
    if (tid < 32) {
        int r = tid >> 2, d = tid & 3;
        float acc = b_o[d];
        #pragma unroll 4
        for (int h = 0; h < 256; h++) acc += sB[r][h] * W_o[h * 4 + d];
        float m = acc;
        m = fmaxf(m, __shfl_xor_sync(0xffffffffu, m, 1));
        m = fmaxf(m, __shfl_xor_sync(0xffffffffu, m, 2));
        float e = expf(acc - m);
        float s = e;
        s += __shfl_xor_sync(0xffffffffu, s, 1);
        s += __shfl_xor_sync(0xffffffffu, s, 2);
        out[(row0 + r) * 4 + d] = acc - m - logf(s);
    }
}

// ---------------------------------------------------------------------------
// Launch
// ---------------------------------------------------------------------------
extern "C" void kernel_launch(void* const* d_in, const int* in_sizes, int n_in,
                              void* d_out, int out_size) {
    const float* x    = (const float*)d_in[0];
    const float* adj  = (const float*)d_in[1];
    const float* W_e1 = (const float*)d_in[2];
    const float* b_e1 = (const float*)d_in[3];
    const float* W_e2 = (const float*)d_in[4];
    const float* b_e2 = (const float*)d_in[5];
    const float* W_n1 = (const float*)d_in[6];
    const float* b_n1 = (const float*)d_in[7];
    const float* W_n2 = (const float*)d_in[8];
    const float* b_n2 = (const float*)d_in[9];
    const float* W_o1 = (const float*)d_in[10];
    const float* b_o1 = (const float*)d_in[11];
    const float* W_o  = (const float*)d_in[12];
    const float* b_o  = (const float*)d_in[13];
    float* out = (float*)d_out;

    prep_uv_kernel<<<(BB * NN * HH) / 256, 256>>>(x, W_e1, b_e1);
    wfrag_kernel<<<32, 256>>>(W_e2);
    edge_mma_kernel<<<BB * NN, 128>>>(adj, b_e2);
    tail_kernel<<<(BB * NN) / 8, 256>>>(x, W_n1, b_n1, W_n2, b_n2,
                                        W_o1, b_o1, W_o, b_o, out);
}

// round 14
// speedup vs baseline: 2.3955x; 1.0772x over previous
#include <cuda_runtime.h>
#include <cuda_bf16.h>
#include <cuda_fp16.h>
#include <cstdint>
#include <math.h>

#define BB 4
#define NN 512
#define DD 4
#define HH 256

// ---------------------------------------------------------------------------
// Device scratch (allocation-free rule)
// ---------------------------------------------------------------------------
__device__ __align__(16) __half g_u16[BB * NN * HH];  // x[b,j]@W_e1[0:4]        (fp16)
__device__ __align__(16) __half g_v16[BB * NN * HH];  // x[b,i]@W_e1[4:8]+b_e1   (fp16)
__device__ __align__(16) float  g_agg[BB * NN * HH];
// mma B-fragment arrays, layout [t(8)][g(32)][lane(32)] -> uint4
// {b0(s=2t), b1(s=2t), b0(s=2t+1), b1(s=2t+1)}
__device__ __align__(16) uint4 g_Wh[8 * 32 * 32];       // W_e2
__device__ __align__(16) uint4 g_Wt[3 * 8 * 32 * 32];   // W_n1, W_n2, W_o1[4:260]

// ---------------------------------------------------------------------------
// PTX wrappers (baseline sm_80-class; compile clean for compute_103)
// ---------------------------------------------------------------------------
__device__ __forceinline__ uint32_t smem_to_u32(const void* p) {
    uint32_t a;
    asm("{ .reg .u64 t; cvta.to.shared.u64 t, %1; cvt.u32.u64 %0, t; }" : "=r"(a) : "l"(p));
    return a;
}

__device__ __forceinline__ void ldm4(uint32_t r[4], uint32_t addr) {
    asm volatile("ldmatrix.sync.aligned.m8n8.x4.shared.b16 {%0,%1,%2,%3}, [%4];"
                 : "=r"(r[0]), "=r"(r[1]), "=r"(r[2]), "=r"(r[3]) : "r"(addr));
}

__device__ __forceinline__ void mma_f16(float c[4], const uint32_t a[4],
                                        uint32_t b0, uint32_t b1) {
    asm volatile(
        "mma.sync.aligned.m16n8k16.row.col.f32.f16.f16.f32 "
        "{%0,%1,%2,%3}, {%4,%5,%6,%7}, {%8,%9}, {%0,%1,%2,%3};"
        : "+f"(c[0]), "+f"(c[1]), "+f"(c[2]), "+f"(c[3])
        : "r"(a[0]), "r"(a[1]), "r"(a[2]), "r"(a[3]), "r"(b0), "r"(b1));
}

__device__ __forceinline__ uint32_t pack_h2(float a, float b) {
    __half2 h = __floats2half2_rn(a, b);
    return *(uint32_t*)&h;
}

__device__ __forceinline__ uint32_t hrelu2(uint32_t va, uint32_t ua) {
    __half2 s = __hadd2(*(const __half2*)&va, *(const __half2*)&ua);
    __half2 z = __float2half2_rn(0.0f);
    __half2 r = __hmax2(s, z);
    return *(uint32_t*)&r;
}

__device__ __forceinline__ void cp_async16(uint32_t dst, const void* src) {
    asm volatile("cp.async.cg.shared.global [%0], [%1], 16;" :: "r"(dst), "l"(src));
}
#define CP_COMMIT() asm volatile("cp.async.commit_group;" ::: "memory")
#define CP_WAIT(N)  asm volatile("cp.async.wait_group %0;" :: "n"(N) : "memory")

// ---------------------------------------------------------------------------
// Kernel A: u, v in fp16
// ---------------------------------------------------------------------------
__global__ void prep_uv_kernel(const float* __restrict__ x,
                               const float* __restrict__ W_e1,
                               const float* __restrict__ b_e1) {
    int idx = blockIdx.x * blockDim.x + threadIdx.x;
    if (idx >= BB * NN * HH) return;
    int h  = idx & (HH - 1);
    int bn = idx >> 8;
    const float* xr = x + bn * DD;
    float su = 0.0f;
    float sv = b_e1[h];
    #pragma unroll
    for (int d = 0; d < DD; d++) {
        float xv = xr[d];
        su += xv * W_e1[d * HH + h];
        sv += xv * W_e1[(DD + d) * HH + h];
    }
    g_u16[idx] = __float2half_rn(su);
    g_v16[idx] = __float2half_rn(sv);
}

// ---------------------------------------------------------------------------
// Kernel W: pack W_e2, W_n1, W_n2, W_o1[4:260] into mma B-fragment layout
// ---------------------------------------------------------------------------
__global__ void wfrag_kernel(const float* __restrict__ W_e2,
                             const float* __restrict__ W_n1,
                             const float* __restrict__ W_n2,
                             const float* __restrict__ W_o1) {
    int idx = blockIdx.x * blockDim.x + threadIdx.x;   // 4 * 8192
    if (idx >= 4 * 8192) return;
    int which = idx >> 13;
    int sub   = idx & 8191;
    int lane = sub & 31;
    int g    = (sub >> 5) & 31;
    int t    = sub >> 10;
    int n  = g * 8 + (lane >> 2);
    int q  = lane & 3;
    int k0 = (2 * t) * 16 + q * 2;
    int k1 = (2 * t + 1) * 16 + q * 2;

    const float* W;
    int rowoff = 0;
    uint4* dst;
    if (which == 0)      { W = W_e2; dst = g_Wh + sub; }
    else if (which == 1) { W = W_n1; dst = g_Wt + sub; }
    else if (which == 2) { W = W_n2; dst = g_Wt + 8192 + sub; }
    else                 { W = W_o1; rowoff = 4; dst = g_Wt + 16384 + sub; }

    uint4 o;
    o.x = pack_h2(W[(rowoff + k0)     * HH + n], W[(rowoff + k0 + 1) * HH + n]);
    o.y = pack_h2(W[(rowoff + k0 + 8) * HH + n], W[(rowoff + k0 + 9) * HH + n]);
    o.z = pack_h2(W[(rowoff + k1)     * HH + n], W[(rowoff + k1 + 1) * HH + n]);
    o.w = pack_h2(W[(rowoff + k1 + 8) * HH + n], W[(rowoff + k1 + 9) * HH + n]);
    *dst = o;
}

// ---------------------------------------------------------------------------
// Kernel E: per (b,j) edge GEMM (unchanged from R12 — best known).
// ---------------------------------------------------------------------------
__global__ __launch_bounds__(128, 2)
void edge_mma_kernel(const float* __restrict__ adj, const float* __restrict__ b_e2) {
    __shared__ __align__(16) __half s_u16[HH];
    __shared__ float s_b2[HH];
    __shared__ float s_adj[NN];
    __shared__ __align__(16) __half sA[2 * 64 * 256];   // two 32KB buffers

    const int bid  = blockIdx.x;          // b*512 + j
    const int b    = bid >> 9;
    const int jj   = bid & (NN - 1);
    const int tid  = threadIdx.x;
    const int warp = tid >> 5;            // owns cols [warp*64, +64)
    const int lane = tid & 31;
    const int rg   = lane >> 2;
    const int q    = lane & 3;
    const int hi4  = lane >> 4;

    const uint32_t aB    = smem_to_u32(sA);
    const __half*  vbase = g_v16 + (size_t)b * NN * HH;

    const int tr_r = warp * 16 + (lane & 15);
    const int tr_h = lane >> 4;
    const uint32_t tr_sw = (uint32_t)(tr_r & 7);

    {
        #pragma unroll
        for (int p = 0; p < 16; p++) {
            int r = warp * 16 + p;
            cp_async16(aB + (uint32_t)r * 512 + ((uint32_t)(lane ^ (r & 7)) << 4),
                       vbase + (size_t)r * HH + lane * 8);
        }
        CP_COMMIT();
    }
    if (tid < 32)
        ((uint4*)s_u16)[tid] = ((const uint4*)(g_u16 + (size_t)bid * HH))[tid];
    s_b2[tid]       = b_e2[tid];
    s_b2[tid + 128] = b_e2[tid + 128];
    {
        #pragma unroll
        for (int p = 0; p < 4; p++) {
            int i = p * 128 + tid;
            s_adj[i] = adj[((size_t)b * NN + i) * NN + jj];
        }
    }
    CP_WAIT(0);
    __syncthreads();
    {
        char* buf0 = (char*)sA;
        #pragma unroll
        for (int p = 0; p < 16; p++) {
            int c16 = tr_h * 16 + p;
            uint32_t off = (uint32_t)tr_r * 512 + ((uint32_t)(c16 ^ tr_sw) << 4);
            uint4 v = *(const uint4*)(buf0 + off);
            uint4 u = *(const uint4*)((const char*)s_u16 + c16 * 16);
            uint4 o;
            o.x = hrelu2(v.x, u.x);
            o.y = hrelu2(v.y, u.y);
            o.z = hrelu2(v.z, u.z);
            o.w = hrelu2(v.w, u.w);
            *(uint4*)(buf0 + off) = o;
        }
    }
    __syncthreads();

    float partial[16];
    #pragma unroll
    for (int c = 0; c < 16; c++) partial[c] = 0.0f;

    #pragma unroll 1
    for (int iter = 0; iter < 8; iter++) {
        const int cur = iter & 1;
        const int nxt = cur ^ 1;
        char* bufN = (char*)sA + nxt * 32768;
        const uint32_t bufNB = aB + (uint32_t)nxt * 32768;

        if (iter < 7) {
            const __half* vg = vbase + (size_t)((iter + 1) * 64) * HH;
            #pragma unroll
            for (int p = 0; p < 16; p++) {
                int r = warp * 16 + p;
                cp_async16(bufNB + (uint32_t)r * 512 + ((uint32_t)(lane ^ (r & 7)) << 4),
                           vg + (size_t)r * HH + lane * 8);
            }
            CP_COMMIT();
        }

        const uint32_t rbase = aB + (uint32_t)cur * 32768 + (uint32_t)(lane & 15) * 512;
        const uint32_t swb   = (uint32_t)(lane & 7);
        float C[4][8][4];
        #pragma unroll
        for (int m = 0; m < 4; m++)
            #pragma unroll
            for (int j = 0; j < 8; j++)
                #pragma unroll
                for (int e = 0; e < 4; e++) C[m][j][e] = 0.0f;

        #pragma unroll 1
        for (int t = 0; t < 8; t++) {
            uint32_t a0[4][4], a1[4][4];
            uint32_t c0 = (uint32_t)(4 * t + hi4);
            #pragma unroll
            for (int m = 0; m < 4; m++) {
                uint32_t rb = rbase + (uint32_t)(m * 16) * 512;
                ldm4(a0[m], rb + (((c0)     ^ swb) << 4));
                ldm4(a1[m], rb + (((c0 + 2) ^ swb) << 4));
            }

            if (iter < 7 && t >= 4) {
                if (t == 4) { CP_WAIT(0); __syncwarp(); }
                #pragma unroll
                for (int p = 0; p < 4; p++) {
                    int c16 = tr_h * 16 + (t - 4) * 4 + p;
                    uint32_t off = (uint32_t)tr_r * 512 + ((uint32_t)(c16 ^ tr_sw) << 4);
                    uint4 v = *(const uint4*)(bufN + off);
                    uint4 u = *(const uint4*)((const char*)s_u16 + c16 * 16);
                    uint4 o;
                    o.x = hrelu2(v.x, u.x);
                    o.y = hrelu2(v.y, u.y);
                    o.z = hrelu2(v.z, u.z);
                    o.w = hrelu2(v.w, u.w);
                    *(uint4*)(bufN + off) = o;
                }
            }

            const uint4* wp = g_Wh + ((t * 32) + warp * 8) * 32 + lane;
            uint4 wfA = wp[0];
            uint4 wfB = wp[32];
            #pragma unroll
            for (int j = 0; j < 8; j++) {
                uint4 wfN;
                if (j < 6) wfN = wp[(j + 2) * 32];
                #pragma unroll
                for (int m = 0; m < 4; m++) {
                    mma_f16(C[m][j], a0[m], wfA.x, wfA.y);
                    mma_f16(C[m][j], a1[m], wfA.z, wfA.w);
                }
                wfA = wfB;
                wfB = wfN;
            }
        }

        #pragma unroll
        for (int m = 0; m < 4; m++) {
            float aw0 = s_adj[iter * 64 + m * 16 + rg];
            float aw1 = s_adj[iter * 64 + m * 16 + rg + 8];
            #pragma unroll
            for (int j = 0; j < 8; j++) {
                float bb0 = s_b2[warp * 64 + j * 8 + q * 2];
                float bb1 = s_b2[warp * 64 + j * 8 + q * 2 + 1];
                partial[j*2+0] += aw0 * fmaxf(C[m][j][0] + bb0, 0.0f)
                                + aw1 * fmaxf(C[m][j][2] + bb0, 0.0f);
                partial[j*2+1] += aw0 * fmaxf(C[m][j][1] + bb1, 0.0f)
                                + aw1 * fmaxf(C[m][j][3] + bb1, 0.0f);
            }
        }

        __syncthreads();
    }

    #pragma unroll
    for (int c = 0; c < 16; c++) {
        float v = partial[c];
        v += __shfl_down_sync(0xffffffffu, v, 16);
        v += __shfl_down_sync(0xffffffffu, v, 8);
        v += __shfl_down_sync(0xffffffffu, v, 4);
        partial[c] = v;
    }
    if (lane < 4) {
        #pragma unroll
        for (int c = 0; c < 16; c++) {
            int col = warp * 64 + (c >> 1) * 8 + lane * 2 + (c & 1);
            g_agg[bid * HH + col] = partial[c];
        }
    }
}

// ---------------------------------------------------------------------------
// Kernel C: tensor-core tail. 128 CTAs x 16 rows, 128 threads (4 warps).
// 3 mma layers (W_n1, W_n2, W_o1-tail) through ping-pong fp16 smem buffers;
// layer 3 adds x@W_o1[0:4]+b_o1 (no relu) into fp32 smem; final 4-col GEMM
// + log_softmax in fp32.
// ---------------------------------------------------------------------------
#define TROWS 16

__global__ __launch_bounds__(128, 4)
void tail_mma_kernel(const float* __restrict__ x,
                     const float* __restrict__ b_n1,
                     const float* __restrict__ b_n2,
                     const float* __restrict__ W_o1,
                     const float* __restrict__ b_o1,
                     const float* __restrict__ W_o,
                     const float* __restrict__ b_o,
                     float* __restrict__ out) {
    __shared__ __align__(16) __half sAB[2][TROWS * 256];  // swizzled, ping-pong
    __shared__ float sOut4[TROWS][260];
    __shared__ float sx[TROWS][4];

    const int row0 = blockIdx.x * TROWS;
    const int tid  = threadIdx.x;
    const int warp = tid >> 5;
    const int lane = tid & 31;
    const int rg   = lane >> 2;
    const int q    = lane & 3;
    const int hi4  = lane >> 4;

    if (tid < TROWS * 4) sx[tid >> 2][tid & 3] = x[row0 * 4 + tid];

    // build A(0) from g_agg (fp32 -> fp16, swizzled; same layout as edge)
    {
        int r   = tid >> 3;            // 0..15
        int seg = (tid & 7) * 32;      // 32-col segment
        const float* src = g_agg + (size_t)(row0 + r) * HH + seg;
        char* dst = (char*)sAB[0] + r * 512;
        int sw = r & 7;
        #pragma unroll
        for (int p = 0; p < 4; p++) {
            float4 f0 = *(const float4*)(src + p * 8);
            float4 f1 = *(const float4*)(src + p * 8 + 4);
            uint4 o;
            o.x = pack_h2(f0.x, f0.y); o.y = pack_h2(f0.z, f0.w);
            o.z = pack_h2(f1.x, f1.y); o.w = pack_h2(f1.z, f1.w);
            int c16 = (seg >> 3) + p;
            *(uint4*)(dst + ((c16 ^ sw) << 4)) = o;
        }
    }
    __syncthreads();

    #pragma unroll 1
    for (int layer = 0; layer < 3; layer++) {
        const uint4* wfrag = g_Wt + (size_t)layer * 8192;
        const uint32_t rbase = smem_to_u32(sAB[layer & 1]) + (uint32_t)(lane & 15) * 512;
        const uint32_t swb   = (uint32_t)(lane & 7);
        char* dstB = (char*)sAB[(layer & 1) ^ 1];

        float C[8][4];
        #pragma unroll
        for (int j = 0; j < 8; j++)
            #pragma unroll
            for (int e = 0; e < 4; e++) C[j][e] = 0.0f;

        #pragma unroll 1
        for (int t = 0; t < 8; t++) {
            uint32_t a0[4], a1[4];
            uint32_t c0 = (uint32_t)(4 * t + hi4);
            ldm4(a0, rbase + (((c0)     ^ swb) << 4));
            ldm4(a1, rbase + (((c0 + 2) ^ swb) << 4));
            const uint4* wp = wfrag + ((t * 32) + warp * 8) * 32 + lane;
            #pragma unroll
            for (int j = 0; j < 8; j++) {
                uint4 wf = wp[j * 32];
                mma_f16(C[j], a0, wf.x, wf.y);
                mma_f16(C[j], a1, wf.z, wf.w);
            }
        }

        if (layer < 2) {
            const float* bias = (layer == 0) ? b_n1 : b_n2;
            #pragma unroll
            for (int j = 0; j < 8; j++) {
                int n0 = warp * 64 + j * 8 + q * 2;
                float bb0 = __ldg(bias + n0);
                float bb1 = __ldg(bias + n0 + 1);
                uint32_t v0 = pack_h2(fmaxf(C[j][0] + bb0, 0.0f),
                                      fmaxf(C[j][1] + bb1, 0.0f));
                uint32_t v1 = pack_h2(fmaxf(C[j][2] + bb0, 0.0f),
                                      fmaxf(C[j][3] + bb1, 0.0f));
                uint32_t c16 = (uint32_t)(warp * 8 + j);
                *(uint32_t*)(dstB + rg * 512       + ((c16 ^ (uint32_t)(rg & 7)) << 4) + q * 4) = v0;
                *(uint32_t*)(dstB + (rg + 8) * 512 + ((c16 ^ (uint32_t)(rg & 7)) << 4) + q * 4) = v1;
            }
        } else {
            // out4 = C + b_o1 + x @ W_o1[0:4]   (no relu), fp32
            #pragma unroll
            for (int j = 0; j < 8; j++) {
                int n0 = warp * 64 + j * 8 + q * 2;
                float t00 = C[j][0] + __ldg(b_o1 + n0);
                float t01 = C[j][1] + __ldg(b_o1 + n0 + 1);
                float t10 = C[j][2] + __ldg(b_o1 + n0);
                float t11 = C[j][3] + __ldg(b_o1 + n0 + 1);
                #pragma unroll
                for (int d = 0; d < 4; d++) {
                    float w0 = __ldg(W_o1 + d * HH + n0);
                    float w1 = __ldg(W_o1 + d * HH + n0 + 1);
                    t00 += sx[rg][d] * w0;     t01 += sx[rg][d] * w1;
                    t10 += sx[rg + 8][d] * w0; t11 += sx[rg + 8][d] * w1;
                }
                sOut4[rg][n0]     = t00;  sOut4[rg][n0 + 1]     = t01;
                sOut4[rg + 8][n0] = t10;  sOut4[rg + 8][n0 + 1] = t11;
            }
        }
        __syncthreads();
    }

    // final: out5 = out4 @ W_o + b_o ; log_softmax over D=4
    if (tid < TROWS * 4) {
        int r = tid >> 2, d = tid & 3;
        float acc = b_o[d];
        #pragma unroll 4
        for (int h = 0; h < 256; h++) acc += sOut4[r][h] * __ldg(W_o + h * 4 + d);
        float m = acc;
        m = fmaxf(m, __shfl_xor_sync(0xffffffffu, m, 1));
        m = fmaxf(m, __shfl_xor_sync(0xffffffffu, m, 2));
        float e = expf(acc - m);
        float s = e;
        s += __shfl_xor_sync(0xffffffffu, s, 1);
        s += __shfl_xor_sync(0xffffffffu, s, 2);
        out[(row0 + r) * 4 + d] = acc - m - logf(s);
    }
}

// ---------------------------------------------------------------------------
// Launch
// ---------------------------------------------------------------------------
extern "C" void kernel_launch(void* const* d_in, const int* in_sizes, int n_in,
                              void* d_out, int out_size) {
    const float* x    = (const float*)d_in[0];
    const float* adj  = (const float*)d_in[1];
    const float* W_e1 = (const float*)d_in[2];
    const float* b_e1 = (const float*)d_in[3];
    const float* W_e2 = (const float*)d_in[4];
    const float* b_e2 = (const float*)d_in[5];
    const float* W_n1 = (const float*)d_in[6];
    const float* b_n1 = (const float*)d_in[7];
    const float* W_n2 = (const float*)d_in[8];
    const float* b_n2 = (const float*)d_in[9];
    const float* W_o1 = (const float*)d_in[10];
    const float* b_o1 = (const float*)d_in[11];
    const float* W_o  = (const float*)d_in[12];
    const float* b_o  = (const float*)d_in[13];
    float* out = (float*)d_out;

    prep_uv_kernel<<<(BB * NN * HH) / 256, 256>>>(x, W_e1, b_e1);
    wfrag_kernel<<<128, 256>>>(W_e2, W_n1, W_n2, W_o1);
    edge_mma_kernel<<<BB * NN, 128>>>(adj, b_e2);
    tail_mma_kernel<<<(BB * NN) / TROWS, 128>>>(x, b_n1, b_n2, W_o1, b_o1,
                                                W_o, b_o, out);
}